// round 3
// baseline (speedup 1.0000x reference)
#include <cuda_runtime.h>
#include <math.h>

typedef unsigned long long u64;

#define BATCH 8
#define NBOX  300
#define TOPK  20
#define HW    512
#define CROPS 64
#define OC    256
#define FCO   4096

// d_out layout (floats): Objects[8,20,4] | Object_features[8,20,4096] | valid[8,20] | fullframe[8,4096]
#define OBJ_OFF   0
#define FEAT_OFF  640
#define VALID_OFF 656000
#define FULL_OFF  656160

#define FULL_BLOCKS 4096
#define CONV_SMEM   101952

__constant__ float c_mean[3] = {0.485f, 0.456f, 0.406f};
__constant__ float c_istd[3] = {1.0f/0.229f, 1.0f/0.224f, 1.0f/0.225f};

__device__ float g_pooled_full[BATCH*OC];
__device__ float g_pooled_crop[BATCH*TOPK*OC];
__device__ float g_crops[BATCH*TOPK*3*CROPS*CROPS];
__device__ float g_Wt[147*OC];          // transposed conv weights: [k][oc]
__device__ float g_job_box[BATCH*TOPK*4];
__device__ int   g_job_b[BATCH*TOPK];
__device__ int   g_job_bk[BATCH*TOPK];
__device__ int   g_njobs;
__device__ int   g_lab64;

// ---------------------------------------------------------------- f32x2 helpers
__device__ __forceinline__ void ffma2(u64 &d, u64 a, u64 b) {
    asm("fma.rn.f32x2 %0, %1, %2, %0;" : "+l"(d) : "l"(a), "l"(b));
}
__device__ __forceinline__ u64 dup2(float a) {
    u64 r; asm("mov.b64 %0, {%1, %1};" : "=l"(r) : "f"(a)); return r;
}
__device__ __forceinline__ void unpack2(u64 v, float &lo, float &hi) {
    asm("mov.b64 {%0, %1}, %2;" : "=f"(lo), "=f"(hi) : "l"(v));
}

// ---------------------------------------------------------------- prep: init + dtype probe + weight transpose
__global__ void prep_kernel(const float* __restrict__ Wc,
                            const long long* __restrict__ lab) {
    int gid = blockIdx.x*256 + threadIdx.x;
    if (gid < BATCH*OC)      g_pooled_full[gid] = 0.f;
    if (gid < BATCH*TOPK*OC) g_pooled_crop[gid] = 0.f;
    if (gid == 0)            g_njobs = 0;
    if (blockIdx.x < 147) {
        int k = blockIdx.x, c = threadIdx.x;
        g_Wt[k*OC + c] = Wc[c*147 + k];
    }
    if (blockIdx.x == 159) {
        // labels dtype probe: first 1200 int64 words == extent of an int32 buffer
        // of 2400 elems (never OOB). Real int64 labels all lie in [0,91).
        __shared__ int bad;
        if (threadIdx.x == 0) bad = 0;
        __syncthreads();
        for (int i = threadIdx.x; i < 1200; i += 256) {
            long long v = lab[i];
            if (v < 0 || v >= 91) bad = 1;
        }
        __syncthreads();
        if (threadIdx.x == 0) g_lab64 = bad ? 0 : 1;
    }
}

// ---------------------------------------------------------------- top-k: one warp per batch
__global__ void topk_kernel(const float* __restrict__ boxes,
                            const float* __restrict__ scores,
                            const void* __restrict__ labels_raw,
                            float* __restrict__ out) {
    int b = blockIdx.x;
    int t = threadIdx.x;      // 0..31
    int lab64 = g_lab64;
    const int*       l32 = (const int*)labels_raw;
    const long long* l64 = (const long long*)labels_raw;

    float v[10];
    #pragma unroll
    for (int r = 0; r < 10; r++) {
        int i = t + 32*r;
        float s = -INFINITY;
        if (i < NBOX) {
            long long l = lab64 ? l64[b*NBOX + i] : (long long)l32[b*NBOX + i];
            bool veh = (l==2)||(l==3)||(l==4)||(l==6)||(l==8);
            float sc = scores[b*NBOX + i];
            if (veh && sc > 0.8f) s = sc;
        }
        v[r] = s;
    }
    for (int k = 0; k < TOPK; k++) {
        float bv = -INFINITY; int bi = 0x7fffffff;
        #pragma unroll
        for (int r = 0; r < 10; r++) {
            int i = t + 32*r;
            if (v[r] > bv) { bv = v[r]; bi = i; }
        }
        #pragma unroll
        for (int o = 16; o > 0; o >>= 1) {
            float ov = __shfl_down_sync(0xffffffffu, bv, o);
            int   oi = __shfl_down_sync(0xffffffffu, bi, o);
            if (ov > bv || (ov == bv && oi < bi)) { bv = ov; bi = oi; }
        }
        bv = __shfl_sync(0xffffffffu, bv, 0);
        bi = __shfl_sync(0xffffffffu, bi, 0);
        bool valid = (bv != -INFINITY);
        if (valid && (bi & 31) == t) {
            int r = bi >> 5;
            #pragma unroll
            for (int rr = 0; rr < 10; rr++) if (rr == r) v[rr] = -INFINITY;
        }
        if (t == 0) {
            float b0=0.f,b1=0.f,b2=0.f,b3=0.f;
            if (valid) {
                const float* bp = boxes + (b*NBOX + bi)*4;
                b0=bp[0]; b1=bp[1]; b2=bp[2]; b3=bp[3];
            }
            int bk = b*TOPK + k;
            out[OBJ_OFF + bk*4+0] = b0;
            out[OBJ_OFF + bk*4+1] = b1;
            out[OBJ_OFF + bk*4+2] = b2;
            out[OBJ_OFF + bk*4+3] = b3;
            out[VALID_OFF + bk]   = valid ? 1.0f : 0.0f;
            if (valid && b2 > b0 && b3 > b1) {
                int pos = atomicAdd(&g_njobs, 1);
                g_job_box[pos*4+0]=b0; g_job_box[pos*4+1]=b1;
                g_job_box[pos*4+2]=b2; g_job_box[pos*4+3]=b3;
                g_job_b[pos]  = b;
                g_job_bk[pos] = bk;
            }
        }
    }
}

// ---------------------------------------------------------------- RoIAlign (normalized on the fly)
__global__ void sample_kernel(const float* __restrict__ x) {
    int j = blockIdx.x;
    if (j >= g_njobs) return;
    int b = g_job_b[j];
    float bx0 = g_job_box[j*4+0], by0 = g_job_box[j*4+1];
    float bx1 = g_job_box[j*4+2], by1 = g_job_box[j*4+3];
    for (int idx = threadIdx.x; idx < 3*CROPS*CROPS; idx += blockDim.x) {
        int c  = idx >> 12;
        int rem = idx & 4095;
        int yi = rem >> 6, xi = rem & 63;
        float ys = by0 + (yi + 0.5f)*(1.0f/CROPS)*(by1 - by0);
        float xs = bx0 + (xi + 0.5f)*(1.0f/CROPS)*(bx1 - bx0);
        float yf = floorf(ys), xf = floorf(xs);
        float wy = ys - yf,  wx = xs - xf;
        int y0 = min(max((int)yf, 0), HW-1); int y1 = min(y0+1, HW-1);
        int x0 = min(max((int)xf, 0), HW-1); int x1 = min(x0+1, HW-1);
        const float* img = x + ((long)b*3 + c)*HW*HW;
        float m = c_mean[c], is = c_istd[c];
        float Ia = (img[y0*HW + x0]-m)*is, Ib = (img[y0*HW + x1]-m)*is;
        float Ic = (img[y1*HW + x0]-m)*is, Id = (img[y1*HW + x1]-m)*is;
        g_crops[j*(3*CROPS*CROPS) + idx] =
            Ia*(1.f-wy)*(1.f-wx) + Ib*(1.f-wy)*wx + Ic*wy*(1.f-wx) + Id*wy*wx;
    }
}

// ---------------------------------------------------------------- unified conv+ReLU+pool (f32x2)
// 128 threads: pxg = t&15 (16 pixel groups), cg = t>>4 (8 channel groups of 8 ch).
// Each thread: 8 px x 8 ch via 32 packed f32x2 accumulators (channel pairs).
__global__ void __launch_bounds__(128) conv_kernel(const float* __restrict__ x,
                                                   const float* __restrict__ bc) {
    extern __shared__ float sm[];
    int t = threadIdx.x;
    int pxg = t & 15, cg = t >> 4;
    int bx = blockIdx.x;

    if (bx < FULL_BLOCKS) {
        // ---------------- fullframe: one output row (128 px) x 64 channels
        int ct = bx & 3; int oy = (bx >> 2) & 127; int b = bx >> 9;
        int c0 = ct*64;
        float* smP = sm;            // 21 planes * 528
        float* smW = sm + 11088;    // 147*64
        int iyb = oy*4 - 1;
        for (int plane = 0; plane < 21; plane++) {
            int cin = plane / 7, ky = plane - cin*7;
            int iy = iyb + ky;
            const float* xr = x + (((long)b*3 + cin)*512 + iy)*512;
            float m = c_mean[cin], is = c_istd[cin];
            float* sp = smP + plane*528;
            bool rowok = (unsigned)iy < 512u;
            for (int p = t; p < 516; p += 128) {
                int ix = p - 1;
                float v = 0.f;
                if (rowok && (unsigned)ix < 512u) v = (xr[ix] - m)*is;
                sp[(p&3)*132 + (p>>2)] = v;
            }
        }
        for (int s = t; s < 9408; s += 128)
            smW[s] = g_Wt[(s>>6)*OC + c0 + (s&63)];
        __syncthreads();

        u64 acc[8][4];
        {
            const u64* bc2 = (const u64*)(bc + c0 + cg*8);
            #pragma unroll
            for (int i = 0; i < 4; i++) {
                u64 bi = bc2[i];
                #pragma unroll
                for (int p = 0; p < 8; p++) acc[p][i] = bi;
            }
        }
        for (int cin = 0; cin < 3; cin++) {
            #pragma unroll
            for (int ky = 0; ky < 7; ky++) {
                const float* pl = smP + (cin*7 + ky)*528 + 2*pxg;
                const float* wk = smW + (cin*7 + ky)*448 + cg*8;
                #pragma unroll
                for (int kx = 0; kx < 7; kx++) {
                    const float* pb = pl + (kx&3)*132 + (kx>>2);
                    const u64* wp = (const u64*)(wk + kx*64);
                    u64 w2[4];
                    #pragma unroll
                    for (int i = 0; i < 4; i++) w2[i] = wp[i];
                    #pragma unroll
                    for (int p = 0; p < 8; p++) {
                        float a = pb[32*(p>>1) + (p&1)];
                        u64 ad = dup2(a);
                        #pragma unroll
                        for (int i = 0; i < 4; i++) ffma2(acc[p][i], ad, w2[i]);
                    }
                }
            }
        }
        #pragma unroll
        for (int i = 0; i < 4; i++) {
            float s0 = 0.f, s1 = 0.f;
            #pragma unroll
            for (int p = 0; p < 8; p++) {
                float lo, hi; unpack2(acc[p][i], lo, hi);
                s0 += fmaxf(lo, 0.f); s1 += fmaxf(hi, 0.f);
            }
            #pragma unroll
            for (int o = 8; o > 0; o >>= 1) {
                s0 += __shfl_down_sync(0xffffffffu, s0, o, 16);
                s1 += __shfl_down_sync(0xffffffffu, s1, o, 16);
            }
            if (pxg == 0) {
                atomicAdd(&g_pooled_full[b*OC + c0 + cg*8 + 2*i],     s0);
                atomicAdd(&g_pooled_full[b*OC + c0 + cg*8 + 2*i + 1], s1);
            }
        }
    } else {
        // ---------------- crop: full 16x16 output x 64 channels (2 passes of 128 px)
        int cx = bx - FULL_BLOCKS;
        int ct = cx & 3; int j = cx >> 2;
        if (j >= g_njobs) return;
        int c0 = ct*64;
        float* smP = sm;            // 201*80 = 16080
        float* smW = sm + 16080;
        const float* crop = g_crops + (long)j*(3*CROPS*CROPS);
        for (int s = t; s < 201*67; s += 128) {
            int row = s / 67; int p = s - row*67;
            int cin = row / 67; int iy = row - cin*67;
            int cy = iy - 1, cxx = p - 1;
            float v = 0.f;
            if ((unsigned)cy < 64u && (unsigned)cxx < 64u)
                v = crop[(cin*64 + cy)*64 + cxx];
            smP[row*80 + (p&3)*20 + (p>>2)] = v;
        }
        for (int s = t; s < 9408; s += 128)
            smW[s] = g_Wt[(s>>6)*OC + c0 + (s&63)];
        __syncthreads();

        u64 bias2[4];
        {
            const u64* bc2 = (const u64*)(bc + c0 + cg*8);
            #pragma unroll
            for (int i = 0; i < 4; i++) bias2[i] = bc2[i];
        }
        float pool[8] = {0.f,0.f,0.f,0.f,0.f,0.f,0.f,0.f};
        for (int pass = 0; pass < 2; pass++) {
            u64 acc[8][4];
            #pragma unroll
            for (int p = 0; p < 8; p++)
                #pragma unroll
                for (int i = 0; i < 4; i++) acc[p][i] = bias2[i];
            int oyv[8], oxv[8];
            #pragma unroll
            for (int p = 0; p < 8; p++) {
                int px = pass*128 + 2*pxg + 32*(p>>1) + (p&1);
                oyv[p] = px >> 4; oxv[p] = px & 15;
            }
            for (int cin = 0; cin < 3; cin++) {
                #pragma unroll
                for (int ky = 0; ky < 7; ky++) {
                    int rb[8];
                    #pragma unroll
                    for (int p = 0; p < 8; p++)
                        rb[p] = (cin*67 + oyv[p]*4 + ky)*80 + oxv[p];
                    const float* wk = smW + (cin*7 + ky)*448 + cg*8;
                    #pragma unroll
                    for (int kx = 0; kx < 7; kx++) {
                        int off = (kx&3)*20 + (kx>>2);
                        const u64* wp = (const u64*)(wk + kx*64);
                        u64 w2[4];
                        #pragma unroll
                        for (int i = 0; i < 4; i++) w2[i] = wp[i];
                        #pragma unroll
                        for (int p = 0; p < 8; p++) {
                            float a = smP[rb[p] + off];
                            u64 ad = dup2(a);
                            #pragma unroll
                            for (int i = 0; i < 4; i++) ffma2(acc[p][i], ad, w2[i]);
                        }
                    }
                }
            }
            #pragma unroll
            for (int i = 0; i < 4; i++) {
                #pragma unroll
                for (int p = 0; p < 8; p++) {
                    float lo, hi; unpack2(acc[p][i], lo, hi);
                    pool[2*i]   += fmaxf(lo, 0.f);
                    pool[2*i+1] += fmaxf(hi, 0.f);
                }
            }
        }
        #pragma unroll
        for (int i = 0; i < 4; i++) {
            float s0 = pool[2*i], s1 = pool[2*i+1];
            #pragma unroll
            for (int o = 8; o > 0; o >>= 1) {
                s0 += __shfl_down_sync(0xffffffffu, s0, o, 16);
                s1 += __shfl_down_sync(0xffffffffu, s1, o, 16);
            }
            if (pxg == 0) {
                g_pooled_crop[j*OC + c0 + cg*8 + 2*i]     = s0;
                g_pooled_crop[j*OC + c0 + cg*8 + 2*i + 1] = s1;
            }
        }
    }
}

// ---------------------------------------------------------------- unified FC
__global__ void __launch_bounds__(256) fc_kernel(const float* __restrict__ Wf,
                                                 const float* __restrict__ bf,
                                                 float* __restrict__ out) {
    int y = blockIdx.y, t = threadIdx.x;
    int o = blockIdx.x*256 + t;
    __shared__ float sp[8*OC];
    if (y == 0) {
        for (int s = t; s < BATCH*OC; s += 256)
            sp[s] = g_pooled_full[s] * (1.0f/16384.0f);
        __syncthreads();
        float acc[8] = {0.f,0.f,0.f,0.f,0.f,0.f,0.f,0.f};
        for (int c = 0; c < OC; c++) {
            float w = Wf[(long)c*FCO + o];
            #pragma unroll
            for (int b2 = 0; b2 < 8; b2++) acc[b2] += sp[b2*OC + c] * w;
        }
        float bias = bf[o];
        #pragma unroll
        for (int b2 = 0; b2 < 8; b2++)
            out[FULL_OFF + b2*FCO + o] = acc[b2] + bias;
    } else {
        int nj = g_njobs;
        int j0 = (y - 1)*8;
        if (j0 >= nj) return;
        for (int s = t; s < 8*OC; s += 256) {
            int jj = s >> 8; int c = s & 255;
            int j = j0 + jj;
            sp[s] = (j < nj) ? g_pooled_crop[j*OC + c] * (1.0f/256.0f) : 0.f;
        }
        __syncthreads();
        float acc[8] = {0.f,0.f,0.f,0.f,0.f,0.f,0.f,0.f};
        for (int c = 0; c < OC; c++) {
            float w = Wf[(long)c*FCO + o];
            #pragma unroll
            for (int jj = 0; jj < 8; jj++) acc[jj] += sp[jj*OC + c] * w;
        }
        float bias = bf[o];
        #pragma unroll
        for (int jj = 0; jj < 8; jj++) {
            int j = j0 + jj;
            if (j < nj)
                out[FEAT_OFF + (long)g_job_bk[j]*FCO + o] = acc[jj] + bias;
        }
    }
}

// ---------------------------------------------------------------- launch
extern "C" void kernel_launch(void* const* d_in, const int* in_sizes, int n_in,
                              void* d_out, int out_size) {
    const float* x      = (const float*)d_in[0];
    const float* boxes  = (const float*)d_in[1];
    const float* scores = (const float*)d_in[2];
    const void*  labels = d_in[3];
    const float* Wc     = (const float*)d_in[4];
    const float* bc     = (const float*)d_in[5];
    const float* Wf     = (const float*)d_in[6];
    const float* bf     = (const float*)d_in[7];
    float* out = (float*)d_out;

    cudaFuncSetAttribute(conv_kernel, cudaFuncAttributeMaxDynamicSharedMemorySize, CONV_SMEM);

    prep_kernel<<<160, 256>>>(Wc, (const long long*)labels);
    topk_kernel<<<BATCH, 32>>>(boxes, scores, labels, out);
    cudaMemsetAsync(out + FEAT_OFF, 0, (size_t)BATCH*TOPK*FCO*sizeof(float));
    sample_kernel<<<BATCH*TOPK, 256>>>(x);
    conv_kernel<<<FULL_BLOCKS + 4*BATCH*TOPK, 128, CONV_SMEM>>>(x, bc);
    fc_kernel<<<dim3(16, 21), 256>>>(Wf, bf, out);
}

// round 4
// speedup vs baseline: 1.5621x; 1.5621x over previous
#include <cuda_runtime.h>
#include <math.h>

typedef unsigned long long u64;

#define BATCH 8
#define NBOX  300
#define TOPK  20
#define HW    512
#define CROPS 64
#define OC    256
#define FCO   4096

// d_out layout (floats): Objects[8,20,4] | Object_features[8,20,4096] | valid[8,20] | fullframe[8,4096]
#define OBJ_OFF   0
#define FEAT_OFF  640
#define VALID_OFF 656000
#define FULL_OFF  656160

#define FULL_BLOCKS 4096            // 4 ct * 128 rows * 8 batch
#define CROP_BLOCKS (BATCH*TOPK*8)  // job * 2 halves * 4 ct
#define CONV_SMEM   44352           // 21 planes * 528 floats (fullframe patch)

__constant__ float c_mean[3] = {0.485f, 0.456f, 0.406f};
__constant__ float c_istd[3] = {1.0f/0.229f, 1.0f/0.224f, 1.0f/0.225f};

__device__ float g_pooled_full[BATCH*OC];
__device__ float g_pooled_crop[BATCH*TOPK*OC];
__device__ float g_crops[BATCH*TOPK*3*CROPS*CROPS];
__device__ __align__(16) float g_Wt[147*OC];   // transposed conv weights: [k][oc]
__device__ float g_job_box[BATCH*TOPK*4];
__device__ int   g_job_b[BATCH*TOPK];
__device__ int   g_job_bk[BATCH*TOPK];
__device__ int   g_njobs;
__device__ int   g_lab64;

// ---------------------------------------------------------------- f32x2 helpers
__device__ __forceinline__ void ffma2(u64 &d, u64 a, u64 b) {
    asm("fma.rn.f32x2 %0, %1, %2, %0;" : "+l"(d) : "l"(a), "l"(b));
}
__device__ __forceinline__ u64 dup2(float a) {
    u64 r; asm("mov.b64 %0, {%1, %1};" : "=l"(r) : "f"(a)); return r;
}
__device__ __forceinline__ void unpack2(u64 v, float &lo, float &hi) {
    asm("mov.b64 {%0, %1}, %2;" : "=f"(lo), "=f"(hi) : "l"(v));
}

// ---------------------------------------------------------------- prep
__global__ void prep_kernel(const float* __restrict__ Wc,
                            const long long* __restrict__ lab) {
    int gid = blockIdx.x*256 + threadIdx.x;
    if (gid < BATCH*OC)      g_pooled_full[gid] = 0.f;
    if (gid < BATCH*TOPK*OC) g_pooled_crop[gid] = 0.f;
    if (gid == 0)            g_njobs = 0;
    if (blockIdx.x < 147) {
        int k = blockIdx.x, c = threadIdx.x;
        g_Wt[k*OC + c] = Wc[c*147 + k];
    }
    if (blockIdx.x == 159) {
        // labels dtype probe: first 1200 int64 words == extent of an int32 buffer
        // of 2400 elems (never OOB). Real int64 labels all lie in [0,91).
        __shared__ int bad;
        if (threadIdx.x == 0) bad = 0;
        __syncthreads();
        for (int i = threadIdx.x; i < 1200; i += 256) {
            long long v = lab[i];
            if (v < 0 || v >= 91) bad = 1;
        }
        __syncthreads();
        if (threadIdx.x == 0) g_lab64 = bad ? 0 : 1;
    }
}

// ---------------------------------------------------------------- top-k: one warp per batch
__global__ void topk_kernel(const float* __restrict__ boxes,
                            const float* __restrict__ scores,
                            const void* __restrict__ labels_raw,
                            float* __restrict__ out) {
    int b = blockIdx.x;
    int t = threadIdx.x;
    int lab64 = g_lab64;
    const int*       l32 = (const int*)labels_raw;
    const long long* l64 = (const long long*)labels_raw;

    float v[10];
    #pragma unroll
    for (int r = 0; r < 10; r++) {
        int i = t + 32*r;
        float s = -INFINITY;
        if (i < NBOX) {
            long long l = lab64 ? l64[b*NBOX + i] : (long long)l32[b*NBOX + i];
            bool veh = (l==2)||(l==3)||(l==4)||(l==6)||(l==8);
            float sc = scores[b*NBOX + i];
            if (veh && sc > 0.8f) s = sc;
        }
        v[r] = s;
    }
    for (int k = 0; k < TOPK; k++) {
        float bv = -INFINITY; int bi = 0x7fffffff;
        #pragma unroll
        for (int r = 0; r < 10; r++) {
            int i = t + 32*r;
            if (v[r] > bv) { bv = v[r]; bi = i; }
        }
        #pragma unroll
        for (int o = 16; o > 0; o >>= 1) {
            float ov = __shfl_down_sync(0xffffffffu, bv, o);
            int   oi = __shfl_down_sync(0xffffffffu, bi, o);
            if (ov > bv || (ov == bv && oi < bi)) { bv = ov; bi = oi; }
        }
        bv = __shfl_sync(0xffffffffu, bv, 0);
        bi = __shfl_sync(0xffffffffu, bi, 0);
        bool valid = (bv != -INFINITY);
        if (valid && (bi & 31) == t) {
            int r = bi >> 5;
            #pragma unroll
            for (int rr = 0; rr < 10; rr++) if (rr == r) v[rr] = -INFINITY;
        }
        if (t == 0) {
            float b0=0.f,b1=0.f,b2=0.f,b3=0.f;
            if (valid) {
                const float* bp = boxes + (b*NBOX + bi)*4;
                b0=bp[0]; b1=bp[1]; b2=bp[2]; b3=bp[3];
            }
            int bk = b*TOPK + k;
            out[OBJ_OFF + bk*4+0] = b0;
            out[OBJ_OFF + bk*4+1] = b1;
            out[OBJ_OFF + bk*4+2] = b2;
            out[OBJ_OFF + bk*4+3] = b3;
            out[VALID_OFF + bk]   = valid ? 1.0f : 0.0f;
            if (valid && b2 > b0 && b3 > b1) {
                int pos = atomicAdd(&g_njobs, 1);
                g_job_box[pos*4+0]=b0; g_job_box[pos*4+1]=b1;
                g_job_box[pos*4+2]=b2; g_job_box[pos*4+3]=b3;
                g_job_b[pos]  = b;
                g_job_bk[pos] = bk;
            }
        }
    }
}

// ---------------------------------------------------------------- RoIAlign (normalized on the fly)
__global__ void sample_kernel(const float* __restrict__ x) {
    int j = blockIdx.x;
    if (j >= g_njobs) return;
    int b = g_job_b[j];
    float bx0 = g_job_box[j*4+0], by0 = g_job_box[j*4+1];
    float bx1 = g_job_box[j*4+2], by1 = g_job_box[j*4+3];
    for (int idx = threadIdx.x; idx < 3*CROPS*CROPS; idx += blockDim.x) {
        int c  = idx >> 12;
        int rem = idx & 4095;
        int yi = rem >> 6, xi = rem & 63;
        float ys = by0 + (yi + 0.5f)*(1.0f/CROPS)*(by1 - by0);
        float xs = bx0 + (xi + 0.5f)*(1.0f/CROPS)*(bx1 - bx0);
        float yf = floorf(ys), xf = floorf(xs);
        float wy = ys - yf,  wx = xs - xf;
        int y0 = min(max((int)yf, 0), HW-1); int y1 = min(y0+1, HW-1);
        int x0 = min(max((int)xf, 0), HW-1); int x1 = min(x0+1, HW-1);
        const float* img = x + ((long)b*3 + c)*HW*HW;
        float m = c_mean[c], is = c_istd[c];
        float Ia = (img[y0*HW + x0]-m)*is, Ib = (img[y0*HW + x1]-m)*is;
        float Ic = (img[y1*HW + x0]-m)*is, Id = (img[y1*HW + x1]-m)*is;
        g_crops[j*(3*CROPS*CROPS) + idx] =
            Ia*(1.f-wy)*(1.f-wx) + Ib*(1.f-wy)*wx + Ic*wy*(1.f-wx) + Id*wy*wx;
    }
}

// ---------------------------------------------------------------- conv+ReLU+pool
// 256 threads = 32 pxg (lanes) x 8 cg (warps). Thread: 4 px (pxg+32m) x 8 ch
// = 16 packed f32x2 accumulators (channel pairs). Patch in smem (phase layout),
// weights via LDG.128 (broadcast within warp), activations lane-stride-1 LDS.
__global__ void __launch_bounds__(256, 4) conv_kernel(const float* __restrict__ x,
                                                      const float* __restrict__ bc) {
    extern __shared__ float sm[];
    int t = threadIdx.x;
    int pxg = t & 31, cg = t >> 5;
    int bx = blockIdx.x;

    if (bx < FULL_BLOCKS) {
        // ------------- fullframe: one output row (128 px) x 64 channels
        int ct = bx & 3; int oy = (bx >> 2) & 127; int b = bx >> 9;
        int c0 = ct*64;
        int iyb = oy*4 - 1;
        for (int plane = 0; plane < 21; plane++) {
            int cin = plane/7, ky = plane - cin*7;
            int iy = iyb + ky;
            const float* xr = x + (((long)b*3 + cin)*512 + iy)*512;
            float m = c_mean[cin], is = c_istd[cin];
            float* sp = sm + plane*528;
            bool rowok = (unsigned)iy < 512u;
            for (int p = t; p < 516; p += 256) {
                int ix = p - 1;
                float v = 0.f;
                if (rowok && (unsigned)ix < 512u) v = (xr[ix] - m)*is;
                sp[(p&3)*132 + (p>>2)] = v;
            }
        }
        __syncthreads();

        u64 acc[4][4];
        {
            const u64* b2 = (const u64*)(bc + c0 + cg*8);
            #pragma unroll
            for (int i = 0; i < 4; i++) {
                u64 bb = b2[i];
                acc[0][i]=bb; acc[1][i]=bb; acc[2][i]=bb; acc[3][i]=bb;
            }
        }
        const float* wbase = g_Wt + c0 + cg*8;
        for (int cin = 0; cin < 3; cin++) {
            const float* plc = sm + cin*7*528 + pxg;
            const float* wc  = wbase + cin*49*OC;
            #pragma unroll
            for (int ky = 0; ky < 7; ky++) {
                #pragma unroll
                for (int kx = 0; kx < 7; kx++) {
                    const float* pl = plc + ky*528 + (kx&3)*132 + (kx>>2);
                    float a0 = pl[0], a1 = pl[32], a2 = pl[64], a3 = pl[96];
                    const ulonglong2* wp = (const ulonglong2*)(wc + (ky*7+kx)*OC);
                    ulonglong2 wA = wp[0], wB = wp[1];
                    u64 d;
                    d = dup2(a0); ffma2(acc[0][0],d,wA.x); ffma2(acc[0][1],d,wA.y); ffma2(acc[0][2],d,wB.x); ffma2(acc[0][3],d,wB.y);
                    d = dup2(a1); ffma2(acc[1][0],d,wA.x); ffma2(acc[1][1],d,wA.y); ffma2(acc[1][2],d,wB.x); ffma2(acc[1][3],d,wB.y);
                    d = dup2(a2); ffma2(acc[2][0],d,wA.x); ffma2(acc[2][1],d,wA.y); ffma2(acc[2][2],d,wB.x); ffma2(acc[2][3],d,wB.y);
                    d = dup2(a3); ffma2(acc[3][0],d,wA.x); ffma2(acc[3][1],d,wA.y); ffma2(acc[3][2],d,wB.x); ffma2(acc[3][3],d,wB.y);
                }
            }
        }
        #pragma unroll
        for (int i = 0; i < 4; i++) {
            float s0 = 0.f, s1 = 0.f;
            #pragma unroll
            for (int m = 0; m < 4; m++) {
                float lo, hi; unpack2(acc[m][i], lo, hi);
                s0 += fmaxf(lo, 0.f); s1 += fmaxf(hi, 0.f);
            }
            #pragma unroll
            for (int o = 16; o > 0; o >>= 1) {
                s0 += __shfl_down_sync(0xffffffffu, s0, o);
                s1 += __shfl_down_sync(0xffffffffu, s1, o);
            }
            if (pxg == 0) {
                atomicAdd(&g_pooled_full[b*OC + c0 + cg*8 + 2*i],     s0);
                atomicAdd(&g_pooled_full[b*OC + c0 + cg*8 + 2*i + 1], s1);
            }
        }
    } else {
        // ------------- crop: half (8 out-rows = 128 px) x 64 channels
        int cx2 = bx - FULL_BLOCKS;
        int ct = cx2 & 3; int half = (cx2 >> 2) & 1; int j = cx2 >> 3;
        if (j >= g_njobs) return;
        int c0 = ct*64;
        const float* crop = g_crops + (long)j*(3*CROPS*CROPS);
        int iy0 = half*32 - 1;
        // patch: 3 cin x 35 rows x (67 px phase-decomposed, row stride 84)
        for (int s = t; s < 105*67; s += 256) {
            int row = s / 67; int p = s - row*67;
            int cin = row / 35; int iyl = row - cin*35;
            int cy = iy0 + iyl, cxx = p - 1;
            float v = 0.f;
            if ((unsigned)cy < 64u && (unsigned)cxx < 64u)
                v = crop[(cin*64 + cy)*64 + cxx];
            sm[row*84 + (p&3)*18 + (p>>2)] = v;
        }
        __syncthreads();

        int rowoff[4];
        #pragma unroll
        for (int m = 0; m < 4; m++) {
            int px = pxg + 32*m;
            rowoff[m] = (px >> 4)*4*84 + (px & 15);
        }
        u64 acc[4][4];
        {
            const u64* b2 = (const u64*)(bc + c0 + cg*8);
            #pragma unroll
            for (int i = 0; i < 4; i++) {
                u64 bb = b2[i];
                acc[0][i]=bb; acc[1][i]=bb; acc[2][i]=bb; acc[3][i]=bb;
            }
        }
        const float* wbase = g_Wt + c0 + cg*8;
        for (int cin = 0; cin < 3; cin++) {
            const float* plc = sm + cin*35*84;
            const float* wc  = wbase + cin*49*OC;
            #pragma unroll
            for (int ky = 0; ky < 7; ky++) {
                #pragma unroll
                for (int kx = 0; kx < 7; kx++) {
                    const float* pl = plc + ky*84 + (kx&3)*18 + (kx>>2);
                    float a0 = pl[rowoff[0]], a1 = pl[rowoff[1]];
                    float a2 = pl[rowoff[2]], a3 = pl[rowoff[3]];
                    const ulonglong2* wp = (const ulonglong2*)(wc + (ky*7+kx)*OC);
                    ulonglong2 wA = wp[0], wB = wp[1];
                    u64 d;
                    d = dup2(a0); ffma2(acc[0][0],d,wA.x); ffma2(acc[0][1],d,wA.y); ffma2(acc[0][2],d,wB.x); ffma2(acc[0][3],d,wB.y);
                    d = dup2(a1); ffma2(acc[1][0],d,wA.x); ffma2(acc[1][1],d,wA.y); ffma2(acc[1][2],d,wB.x); ffma2(acc[1][3],d,wB.y);
                    d = dup2(a2); ffma2(acc[2][0],d,wA.x); ffma2(acc[2][1],d,wA.y); ffma2(acc[2][2],d,wB.x); ffma2(acc[2][3],d,wB.y);
                    d = dup2(a3); ffma2(acc[3][0],d,wA.x); ffma2(acc[3][1],d,wA.y); ffma2(acc[3][2],d,wB.x); ffma2(acc[3][3],d,wB.y);
                }
            }
        }
        #pragma unroll
        for (int i = 0; i < 4; i++) {
            float s0 = 0.f, s1 = 0.f;
            #pragma unroll
            for (int m = 0; m < 4; m++) {
                float lo, hi; unpack2(acc[m][i], lo, hi);
                s0 += fmaxf(lo, 0.f); s1 += fmaxf(hi, 0.f);
            }
            #pragma unroll
            for (int o = 16; o > 0; o >>= 1) {
                s0 += __shfl_down_sync(0xffffffffu, s0, o);
                s1 += __shfl_down_sync(0xffffffffu, s1, o);
            }
            if (pxg == 0) {
                atomicAdd(&g_pooled_crop[j*OC + c0 + cg*8 + 2*i],     s0);
                atomicAdd(&g_pooled_crop[j*OC + c0 + cg*8 + 2*i + 1], s1);
            }
        }
    }
}

// ---------------------------------------------------------------- unified FC
__global__ void __launch_bounds__(256) fc_kernel(const float* __restrict__ Wf,
                                                 const float* __restrict__ bf,
                                                 float* __restrict__ out) {
    int y = blockIdx.y, t = threadIdx.x;
    int o = blockIdx.x*256 + t;
    __shared__ float sp[8*OC];
    if (y == 0) {
        for (int s = t; s < BATCH*OC; s += 256)
            sp[s] = g_pooled_full[s] * (1.0f/16384.0f);
        __syncthreads();
        float acc[8] = {0.f,0.f,0.f,0.f,0.f,0.f,0.f,0.f};
        for (int c = 0; c < OC; c++) {
            float w = Wf[(long)c*FCO + o];
            #pragma unroll
            for (int b2 = 0; b2 < 8; b2++) acc[b2] += sp[b2*OC + c] * w;
        }
        float bias = bf[o];
        #pragma unroll
        for (int b2 = 0; b2 < 8; b2++)
            out[FULL_OFF + b2*FCO + o] = acc[b2] + bias;
    } else {
        int nj = g_njobs;
        int j0 = (y - 1)*8;
        if (j0 >= nj) return;
        for (int s = t; s < 8*OC; s += 256) {
            int jj = s >> 8; int c = s & 255;
            int j = j0 + jj;
            sp[s] = (j < nj) ? g_pooled_crop[j*OC + c] * (1.0f/256.0f) : 0.f;
        }
        __syncthreads();
        float acc[8] = {0.f,0.f,0.f,0.f,0.f,0.f,0.f,0.f};
        for (int c = 0; c < OC; c++) {
            float w = Wf[(long)c*FCO + o];
            #pragma unroll
            for (int jj = 0; jj < 8; jj++) acc[jj] += sp[jj*OC + c] * w;
        }
        float bias = bf[o];
        #pragma unroll
        for (int jj = 0; jj < 8; jj++) {
            int j = j0 + jj;
            if (j < nj)
                out[FEAT_OFF + (long)g_job_bk[j]*FCO + o] = acc[jj] + bias;
        }
    }
}

// ---------------------------------------------------------------- launch
extern "C" void kernel_launch(void* const* d_in, const int* in_sizes, int n_in,
                              void* d_out, int out_size) {
    const float* x      = (const float*)d_in[0];
    const float* boxes  = (const float*)d_in[1];
    const float* scores = (const float*)d_in[2];
    const void*  labels = d_in[3];
    const float* Wc     = (const float*)d_in[4];
    const float* bc     = (const float*)d_in[5];
    const float* Wf     = (const float*)d_in[6];
    const float* bf     = (const float*)d_in[7];
    float* out = (float*)d_out;

    prep_kernel<<<160, 256>>>(Wc, (const long long*)labels);
    topk_kernel<<<BATCH, 32>>>(boxes, scores, labels, out);
    cudaMemsetAsync(out + FEAT_OFF, 0, (size_t)BATCH*TOPK*FCO*sizeof(float));
    sample_kernel<<<BATCH*TOPK, 256>>>(x);
    conv_kernel<<<FULL_BLOCKS + CROP_BLOCKS, 256, CONV_SMEM>>>(x, bc);
    fc_kernel<<<dim3(16, 21), 256>>>(Wf, bf, out);
}

// round 5
// speedup vs baseline: 1.5941x; 1.0205x over previous
#include <cuda_runtime.h>
#include <math.h>

typedef unsigned long long u64;

#define BATCH 8
#define NBOX  300
#define TOPK  20
#define HW    512
#define CROPS 64
#define OC    256
#define FCO   4096

// d_out layout (floats): Objects[8,20,4] | Object_features[8,20,4096] | valid[8,20] | fullframe[8,4096]
#define OBJ_OFF   0
#define FEAT_OFF  640
#define VALID_OFF 656000
#define FULL_OFF  656160

#define FULL_BLOCKS 2048            // 2 ct * 128 rows * 8 batch
#define CROP_BLOCKS (BATCH*TOPK*4)  // job * 2 halves * 2 ct
#define CONV_SMEM   44352           // 21 planes * 528 floats (fullframe patch)

__constant__ float c_mean[3] = {0.485f, 0.456f, 0.406f};
__constant__ float c_istd[3] = {1.0f/0.229f, 1.0f/0.224f, 1.0f/0.225f};

__device__ float g_pooled_full[BATCH*OC];
__device__ float g_pooled_crop[BATCH*TOPK*OC];
__device__ float g_crops[BATCH*TOPK*3*CROPS*CROPS];
__device__ __align__(16) float g_Wt[147*OC];   // transposed conv weights: [k][oc]
__device__ float g_job_box[BATCH*TOPK*4];
__device__ int   g_job_b[BATCH*TOPK];
__device__ int   g_job_bk[BATCH*TOPK];
__device__ int   g_njobs;
__device__ int   g_lab64;

// ---------------------------------------------------------------- f32x2 helpers
__device__ __forceinline__ void ffma2(u64 &d, u64 a, u64 b) {
    asm("fma.rn.f32x2 %0, %1, %2, %0;" : "+l"(d) : "l"(a), "l"(b));
}
__device__ __forceinline__ u64 dup2(float a) {
    u64 r; asm("mov.b64 %0, {%1, %1};" : "=l"(r) : "f"(a)); return r;
}
__device__ __forceinline__ void unpack2(u64 v, float &lo, float &hi) {
    asm("mov.b64 {%0, %1}, %2;" : "=f"(lo), "=f"(hi) : "l"(v));
}

// ---------------------------------------------------------------- prep
__global__ void prep_kernel(const float* __restrict__ Wc,
                            const long long* __restrict__ lab) {
    int gid = blockIdx.x*256 + threadIdx.x;
    if (gid < BATCH*OC)      g_pooled_full[gid] = 0.f;
    if (gid < BATCH*TOPK*OC) g_pooled_crop[gid] = 0.f;
    if (gid == 0)            g_njobs = 0;
    if (blockIdx.x < 147) {
        int k = blockIdx.x, c = threadIdx.x;
        g_Wt[k*OC + c] = Wc[c*147 + k];
    }
    if (blockIdx.x == 159) {
        // labels dtype probe: first 1200 int64 words == extent of an int32 buffer
        // of 2400 elems (never OOB). Real int64 labels all lie in [0,91).
        __shared__ int bad;
        if (threadIdx.x == 0) bad = 0;
        __syncthreads();
        for (int i = threadIdx.x; i < 1200; i += 256) {
            long long v = lab[i];
            if (v < 0 || v >= 91) bad = 1;
        }
        __syncthreads();
        if (threadIdx.x == 0) g_lab64 = bad ? 0 : 1;
    }
}

// ---------------------------------------------------------------- top-k: one warp per batch
__global__ void topk_kernel(const float* __restrict__ boxes,
                            const float* __restrict__ scores,
                            const void* __restrict__ labels_raw,
                            float* __restrict__ out) {
    int b = blockIdx.x;
    int t = threadIdx.x;
    int lab64 = g_lab64;
    const int*       l32 = (const int*)labels_raw;
    const long long* l64 = (const long long*)labels_raw;

    float v[10];
    #pragma unroll
    for (int r = 0; r < 10; r++) {
        int i = t + 32*r;
        float s = -INFINITY;
        if (i < NBOX) {
            long long l = lab64 ? l64[b*NBOX + i] : (long long)l32[b*NBOX + i];
            bool veh = (l==2)||(l==3)||(l==4)||(l==6)||(l==8);
            float sc = scores[b*NBOX + i];
            if (veh && sc > 0.8f) s = sc;
        }
        v[r] = s;
    }
    for (int k = 0; k < TOPK; k++) {
        float bv = -INFINITY; int bi = 0x7fffffff;
        #pragma unroll
        for (int r = 0; r < 10; r++) {
            int i = t + 32*r;
            if (v[r] > bv) { bv = v[r]; bi = i; }
        }
        #pragma unroll
        for (int o = 16; o > 0; o >>= 1) {
            float ov = __shfl_down_sync(0xffffffffu, bv, o);
            int   oi = __shfl_down_sync(0xffffffffu, bi, o);
            if (ov > bv || (ov == bv && oi < bi)) { bv = ov; bi = oi; }
        }
        bv = __shfl_sync(0xffffffffu, bv, 0);
        bi = __shfl_sync(0xffffffffu, bi, 0);
        bool valid = (bv != -INFINITY);
        if (valid && (bi & 31) == t) {
            int r = bi >> 5;
            #pragma unroll
            for (int rr = 0; rr < 10; rr++) if (rr == r) v[rr] = -INFINITY;
        }
        if (t == 0) {
            float b0=0.f,b1=0.f,b2=0.f,b3=0.f;
            if (valid) {
                const float* bp = boxes + (b*NBOX + bi)*4;
                b0=bp[0]; b1=bp[1]; b2=bp[2]; b3=bp[3];
            }
            int bk = b*TOPK + k;
            out[OBJ_OFF + bk*4+0] = b0;
            out[OBJ_OFF + bk*4+1] = b1;
            out[OBJ_OFF + bk*4+2] = b2;
            out[OBJ_OFF + bk*4+3] = b3;
            out[VALID_OFF + bk]   = valid ? 1.0f : 0.0f;
            if (valid && b2 > b0 && b3 > b1) {
                int pos = atomicAdd(&g_njobs, 1);
                g_job_box[pos*4+0]=b0; g_job_box[pos*4+1]=b1;
                g_job_box[pos*4+2]=b2; g_job_box[pos*4+3]=b3;
                g_job_b[pos]  = b;
                g_job_bk[pos] = bk;
            }
        }
    }
}

// ---------------------------------------------------------------- RoIAlign (normalized on the fly)
__global__ void sample_kernel(const float* __restrict__ x) {
    int j = blockIdx.x;
    if (j >= g_njobs) return;
    int b = g_job_b[j];
    float bx0 = g_job_box[j*4+0], by0 = g_job_box[j*4+1];
    float bx1 = g_job_box[j*4+2], by1 = g_job_box[j*4+3];
    for (int idx = threadIdx.x; idx < 3*CROPS*CROPS; idx += blockDim.x) {
        int c  = idx >> 12;
        int rem = idx & 4095;
        int yi = rem >> 6, xi = rem & 63;
        float ys = by0 + (yi + 0.5f)*(1.0f/CROPS)*(by1 - by0);
        float xs = bx0 + (xi + 0.5f)*(1.0f/CROPS)*(bx1 - bx0);
        float yf = floorf(ys), xf = floorf(xs);
        float wy = ys - yf,  wx = xs - xf;
        int y0 = min(max((int)yf, 0), HW-1); int y1 = min(y0+1, HW-1);
        int x0 = min(max((int)xf, 0), HW-1); int x1 = min(x0+1, HW-1);
        const float* img = x + ((long)b*3 + c)*HW*HW;
        float m = c_mean[c], is = c_istd[c];
        float Ia = (img[y0*HW + x0]-m)*is, Ib = (img[y0*HW + x1]-m)*is;
        float Ic = (img[y1*HW + x0]-m)*is, Id = (img[y1*HW + x1]-m)*is;
        g_crops[j*(3*CROPS*CROPS) + idx] =
            Ia*(1.f-wy)*(1.f-wx) + Ib*(1.f-wy)*wx + Ic*wy*(1.f-wx) + Id*wy*wx;
    }
}

// ---------------------------------------------------------------- conv+ReLU+pool
// 256 threads = 32 px lanes x 8 warps; each warp owns 16 channels (8 ch-pairs).
// Thread: 4 px (pxg+32m) x 16 ch = 32 packed f32x2 accumulators.
// Per tap: 4 stride-1 LDS + 4 broadcast LDG.128 per warp -> ~50% L1 at ~94% fma.
__global__ void __launch_bounds__(256, 2) conv_kernel(const float* __restrict__ x,
                                                      const float* __restrict__ bc) {
    extern __shared__ float sm[];
    int t = threadIdx.x;
    int pxg = t & 31, cg = t >> 5;
    int bx = blockIdx.x;

    if (bx < FULL_BLOCKS) {
        // ------------- fullframe: one output row (128 px) x 128 channels
        int ct = bx & 1; int oy = (bx >> 1) & 127; int b = bx >> 8;
        int c0 = ct*128;
        int iyb = oy*4 - 1;
        for (int plane = 0; plane < 21; plane++) {
            int cin = plane/7, ky = plane - cin*7;
            int iy = iyb + ky;
            const float* xr = x + (((long)b*3 + cin)*512 + iy)*512;
            float m = c_mean[cin], is = c_istd[cin];
            float* sp = sm + plane*528;
            bool rowok = (unsigned)iy < 512u;
            for (int p = t; p < 516; p += 256) {
                int ix = p - 1;
                float v = 0.f;
                if (rowok && (unsigned)ix < 512u) v = (xr[ix] - m)*is;
                sp[(p&3)*132 + (p>>2)] = v;
            }
        }
        __syncthreads();

        u64 acc[4][8];
        {
            const u64* b2 = (const u64*)(bc + c0 + cg*16);
            #pragma unroll
            for (int i = 0; i < 8; i++) {
                u64 bb = b2[i];
                acc[0][i]=bb; acc[1][i]=bb; acc[2][i]=bb; acc[3][i]=bb;
            }
        }
        const float* wbase = g_Wt + c0 + cg*16;
        for (int cin = 0; cin < 3; cin++) {
            const float* plc = sm + cin*7*528 + pxg;
            const float* wc  = wbase + cin*49*OC;
            #pragma unroll
            for (int ky = 0; ky < 7; ky++) {
                #pragma unroll
                for (int kx = 0; kx < 7; kx++) {
                    const float* pl = plc + ky*528 + (kx&3)*132 + (kx>>2);
                    float a0 = pl[0], a1 = pl[32], a2 = pl[64], a3 = pl[96];
                    const ulonglong2* wp = (const ulonglong2*)(wc + (ky*7+kx)*OC);
                    ulonglong2 wA = wp[0], wB = wp[1], wC = wp[2], wD = wp[3];
                    u64 d;
                    d = dup2(a0);
                    ffma2(acc[0][0],d,wA.x); ffma2(acc[0][1],d,wA.y); ffma2(acc[0][2],d,wB.x); ffma2(acc[0][3],d,wB.y);
                    ffma2(acc[0][4],d,wC.x); ffma2(acc[0][5],d,wC.y); ffma2(acc[0][6],d,wD.x); ffma2(acc[0][7],d,wD.y);
                    d = dup2(a1);
                    ffma2(acc[1][0],d,wA.x); ffma2(acc[1][1],d,wA.y); ffma2(acc[1][2],d,wB.x); ffma2(acc[1][3],d,wB.y);
                    ffma2(acc[1][4],d,wC.x); ffma2(acc[1][5],d,wC.y); ffma2(acc[1][6],d,wD.x); ffma2(acc[1][7],d,wD.y);
                    d = dup2(a2);
                    ffma2(acc[2][0],d,wA.x); ffma2(acc[2][1],d,wA.y); ffma2(acc[2][2],d,wB.x); ffma2(acc[2][3],d,wB.y);
                    ffma2(acc[2][4],d,wC.x); ffma2(acc[2][5],d,wC.y); ffma2(acc[2][6],d,wD.x); ffma2(acc[2][7],d,wD.y);
                    d = dup2(a3);
                    ffma2(acc[3][0],d,wA.x); ffma2(acc[3][1],d,wA.y); ffma2(acc[3][2],d,wB.x); ffma2(acc[3][3],d,wB.y);
                    ffma2(acc[3][4],d,wC.x); ffma2(acc[3][5],d,wC.y); ffma2(acc[3][6],d,wD.x); ffma2(acc[3][7],d,wD.y);
                }
            }
        }
        #pragma unroll
        for (int i = 0; i < 8; i++) {
            float s0 = 0.f, s1 = 0.f;
            #pragma unroll
            for (int m = 0; m < 4; m++) {
                float lo, hi; unpack2(acc[m][i], lo, hi);
                s0 += fmaxf(lo, 0.f); s1 += fmaxf(hi, 0.f);
            }
            #pragma unroll
            for (int o = 16; o > 0; o >>= 1) {
                s0 += __shfl_down_sync(0xffffffffu, s0, o);
                s1 += __shfl_down_sync(0xffffffffu, s1, o);
            }
            if (pxg == 0) {
                atomicAdd(&g_pooled_full[b*OC + c0 + cg*16 + 2*i],     s0);
                atomicAdd(&g_pooled_full[b*OC + c0 + cg*16 + 2*i + 1], s1);
            }
        }
    } else {
        // ------------- crop: half (8 out-rows = 128 px) x 128 channels
        int cx2 = bx - FULL_BLOCKS;
        int ct = cx2 & 1; int half = (cx2 >> 1) & 1; int j = cx2 >> 2;
        if (j >= g_njobs) return;
        int c0 = ct*128;
        const float* crop = g_crops + (long)j*(3*CROPS*CROPS);
        int iy0 = half*32 - 1;
        // patch: 3 cin x 35 rows x (67 px phase-decomposed, row stride 84)
        for (int s = t; s < 105*67; s += 256) {
            int row = s / 67; int p = s - row*67;
            int cin = row / 35; int iyl = row - cin*35;
            int cy = iy0 + iyl, cxx = p - 1;
            float v = 0.f;
            if ((unsigned)cy < 64u && (unsigned)cxx < 64u)
                v = crop[(cin*64 + cy)*64 + cxx];
            sm[row*84 + (p&3)*18 + (p>>2)] = v;
        }
        __syncthreads();

        int rowoff[4];
        #pragma unroll
        for (int m = 0; m < 4; m++) {
            int px = pxg + 32*m;
            rowoff[m] = (px >> 4)*4*84 + (px & 15);
        }
        u64 acc[4][8];
        {
            const u64* b2 = (const u64*)(bc + c0 + cg*16);
            #pragma unroll
            for (int i = 0; i < 8; i++) {
                u64 bb = b2[i];
                acc[0][i]=bb; acc[1][i]=bb; acc[2][i]=bb; acc[3][i]=bb;
            }
        }
        const float* wbase = g_Wt + c0 + cg*16;
        for (int cin = 0; cin < 3; cin++) {
            const float* plc = sm + cin*35*84;
            const float* wc  = wbase + cin*49*OC;
            #pragma unroll
            for (int ky = 0; ky < 7; ky++) {
                #pragma unroll
                for (int kx = 0; kx < 7; kx++) {
                    const float* pl = plc + ky*84 + (kx&3)*18 + (kx>>2);
                    float a0 = pl[rowoff[0]], a1 = pl[rowoff[1]];
                    float a2 = pl[rowoff[2]], a3 = pl[rowoff[3]];
                    const ulonglong2* wp = (const ulonglong2*)(wc + (ky*7+kx)*OC);
                    ulonglong2 wA = wp[0], wB = wp[1], wC = wp[2], wD = wp[3];
                    u64 d;
                    d = dup2(a0);
                    ffma2(acc[0][0],d,wA.x); ffma2(acc[0][1],d,wA.y); ffma2(acc[0][2],d,wB.x); ffma2(acc[0][3],d,wB.y);
                    ffma2(acc[0][4],d,wC.x); ffma2(acc[0][5],d,wC.y); ffma2(acc[0][6],d,wD.x); ffma2(acc[0][7],d,wD.y);
                    d = dup2(a1);
                    ffma2(acc[1][0],d,wA.x); ffma2(acc[1][1],d,wA.y); ffma2(acc[1][2],d,wB.x); ffma2(acc[1][3],d,wB.y);
                    ffma2(acc[1][4],d,wC.x); ffma2(acc[1][5],d,wC.y); ffma2(acc[1][6],d,wD.x); ffma2(acc[1][7],d,wD.y);
                    d = dup2(a2);
                    ffma2(acc[2][0],d,wA.x); ffma2(acc[2][1],d,wA.y); ffma2(acc[2][2],d,wB.x); ffma2(acc[2][3],d,wB.y);
                    ffma2(acc[2][4],d,wC.x); ffma2(acc[2][5],d,wC.y); ffma2(acc[2][6],d,wD.x); ffma2(acc[2][7],d,wD.y);
                    d = dup2(a3);
                    ffma2(acc[3][0],d,wA.x); ffma2(acc[3][1],d,wA.y); ffma2(acc[3][2],d,wB.x); ffma2(acc[3][3],d,wB.y);
                    ffma2(acc[3][4],d,wC.x); ffma2(acc[3][5],d,wC.y); ffma2(acc[3][6],d,wD.x); ffma2(acc[3][7],d,wD.y);
                }
            }
        }
        #pragma unroll
        for (int i = 0; i < 8; i++) {
            float s0 = 0.f, s1 = 0.f;
            #pragma unroll
            for (int m = 0; m < 4; m++) {
                float lo, hi; unpack2(acc[m][i], lo, hi);
                s0 += fmaxf(lo, 0.f); s1 += fmaxf(hi, 0.f);
            }
            #pragma unroll
            for (int o = 16; o > 0; o >>= 1) {
                s0 += __shfl_down_sync(0xffffffffu, s0, o);
                s1 += __shfl_down_sync(0xffffffffu, s1, o);
            }
            if (pxg == 0) {
                atomicAdd(&g_pooled_crop[j*OC + c0 + cg*16 + 2*i],     s0);
                atomicAdd(&g_pooled_crop[j*OC + c0 + cg*16 + 2*i + 1], s1);
            }
        }
    }
}

// ---------------------------------------------------------------- unified FC
__global__ void __launch_bounds__(256) fc_kernel(const float* __restrict__ Wf,
                                                 const float* __restrict__ bf,
                                                 float* __restrict__ out) {
    int y = blockIdx.y, t = threadIdx.x;
    int o = blockIdx.x*256 + t;
    __shared__ float sp[8*OC];
    if (y == 0) {
        for (int s = t; s < BATCH*OC; s += 256)
            sp[s] = g_pooled_full[s] * (1.0f/16384.0f);
        __syncthreads();
        float acc[8] = {0.f,0.f,0.f,0.f,0.f,0.f,0.f,0.f};
        for (int c = 0; c < OC; c++) {
            float w = Wf[(long)c*FCO + o];
            #pragma unroll
            for (int b2 = 0; b2 < 8; b2++) acc[b2] += sp[b2*OC + c] * w;
        }
        float bias = bf[o];
        #pragma unroll
        for (int b2 = 0; b2 < 8; b2++)
            out[FULL_OFF + b2*FCO + o] = acc[b2] + bias;
    } else {
        int nj = g_njobs;
        int j0 = (y - 1)*8;
        if (j0 >= nj) return;
        for (int s = t; s < 8*OC; s += 256) {
            int jj = s >> 8; int c = s & 255;
            int j = j0 + jj;
            sp[s] = (j < nj) ? g_pooled_crop[j*OC + c] * (1.0f/256.0f) : 0.f;
        }
        __syncthreads();
        float acc[8] = {0.f,0.f,0.f,0.f,0.f,0.f,0.f,0.f};
        for (int c = 0; c < OC; c++) {
            float w = Wf[(long)c*FCO + o];
            #pragma unroll
            for (int jj = 0; jj < 8; jj++) acc[jj] += sp[jj*OC + c] * w;
        }
        float bias = bf[o];
        #pragma unroll
        for (int jj = 0; jj < 8; jj++) {
            int j = j0 + jj;
            if (j < nj)
                out[FEAT_OFF + (long)g_job_bk[j]*FCO + o] = acc[jj] + bias;
        }
    }
}

// ---------------------------------------------------------------- launch
extern "C" void kernel_launch(void* const* d_in, const int* in_sizes, int n_in,
                              void* d_out, int out_size) {
    const float* x      = (const float*)d_in[0];
    const float* boxes  = (const float*)d_in[1];
    const float* scores = (const float*)d_in[2];
    const void*  labels = d_in[3];
    const float* Wc     = (const float*)d_in[4];
    const float* bc     = (const float*)d_in[5];
    const float* Wf     = (const float*)d_in[6];
    const float* bf     = (const float*)d_in[7];
    float* out = (float*)d_out;

    prep_kernel<<<160, 256>>>(Wc, (const long long*)labels);
    topk_kernel<<<BATCH, 32>>>(boxes, scores, labels, out);
    cudaMemsetAsync(out + FEAT_OFF, 0, (size_t)BATCH*TOPK*FCO*sizeof(float));
    sample_kernel<<<BATCH*TOPK, 256>>>(x);
    conv_kernel<<<FULL_BLOCKS + CROP_BLOCKS, 256, CONV_SMEM>>>(x, bc);
    fc_kernel<<<dim3(16, 21), 256>>>(Wf, bf, out);
}

// round 7
// speedup vs baseline: 2.4849x; 1.5588x over previous
#include <cuda_runtime.h>
#include <math.h>
#include <stdint.h>

typedef unsigned long long u64;

#define BATCH 8
#define NBOX  300
#define TOPK  20
#define HW    512
#define CROPS 64
#define OC    256
#define FCO   4096

// d_out layout (floats): Objects[8,20,4] | Object_features[8,20,4096] | valid[8,20] | fullframe[8,4096]
#define OBJ_OFF   0
#define FEAT_OFF  640
#define VALID_OFF 656000
#define FULL_OFF  656160

#define KPAD 160                      // 147 -> 160 (20 k-steps of 8)
#define BSMEM_FLOATS (20*8*32*4)      // 20480 floats = 81920 B
#define CROP_BLOCKS (BATCH*TOPK*4)    // job * 2 halves * 2 ct
#define CROP_SMEM   35280             // 105*84 floats

__constant__ float c_mean[3] = {0.485f, 0.456f, 0.406f};
__constant__ float c_istd[3] = {1.0f/0.229f, 1.0f/0.224f, 1.0f/0.225f};

__device__ float g_pooled_full[BATCH*OC];
__device__ float g_pooled_crop[BATCH*TOPK*OC];
__device__ float g_crops[BATCH*TOPK*3*CROPS*CROPS];
__device__ __align__(16) float g_Wt[147*OC];        // [k][oc] for scalar crop conv
__device__ __align__(16) float g_Wfrag[2*20*8*32*4]; // mma-fragment-ordered weights [ct][s][Ml][lane][reg]
__device__ float g_job_box[BATCH*TOPK*4];
__device__ int   g_job_b[BATCH*TOPK];
__device__ int   g_job_bk[BATCH*TOPK];
__device__ int   g_njobs;
__device__ int   g_lab64;

// ---------------------------------------------------------------- f32x2 helpers (crop path)
__device__ __forceinline__ void ffma2(u64 &d, u64 a, u64 b) {
    asm("fma.rn.f32x2 %0, %1, %2, %0;" : "+l"(d) : "l"(a), "l"(b));
}
__device__ __forceinline__ u64 dup2(float a) {
    u64 r; asm("mov.b64 %0, {%1, %1};" : "=l"(r) : "f"(a)); return r;
}
__device__ __forceinline__ void unpack2(u64 v, float &lo, float &hi) {
    asm("mov.b64 {%0, %1}, %2;" : "=f"(lo), "=f"(hi) : "l"(v));
}
// tf32 mma: D[16oc x 8px] += A[16x8] * B[8k x 8px]
__device__ __forceinline__ void mma_tf32(float* d, const uint32_t* a, uint32_t b0, uint32_t b1) {
    asm volatile(
        "mma.sync.aligned.m16n8k8.row.col.f32.tf32.tf32.f32 "
        "{%0,%1,%2,%3}, {%4,%5,%6,%7}, {%8,%9}, {%0,%1,%2,%3};"
        : "+f"(d[0]), "+f"(d[1]), "+f"(d[2]), "+f"(d[3])
        : "r"(a[0]), "r"(a[1]), "r"(a[2]), "r"(a[3]), "r"(b0), "r"(b1));
}

// ---------------------------------------------------------------- prep
__global__ void prep_kernel(const float* __restrict__ Wc,
                            const long long* __restrict__ lab) {
    int gid = blockIdx.x*256 + threadIdx.x;     // 0..40959
    if (gid < BATCH*OC)      g_pooled_full[gid] = 0.f;
    if (gid < BATCH*TOPK*OC) g_pooled_crop[gid] = 0.f;
    if (gid == 0)            g_njobs = 0;
    // transposed weights for scalar crop conv
    if (blockIdx.x < 147) {
        int k = blockIdx.x, c = threadIdx.x;
        g_Wt[k*OC + c] = Wc[c*147 + k];
    }
    // fragment-ordered weights for tf32 mma: index = (((ct*20+s)*8+Ml)*32+lane)*4+reg
    {
        int reg  = gid & 3;
        int lane = (gid >> 2) & 31;
        int Ml   = (gid >> 7) & 7;
        int s    = (gid >> 10) % 20;
        int ct   = gid / 20480;
        int oc = ct*128 + Ml*16 + (lane >> 2) + (reg & 1)*8;
        int k  = s*8 + (lane & 3) + (reg >> 1)*4;
        g_Wfrag[gid] = (k < 147) ? Wc[oc*147 + k] : 0.f;
    }
    if (blockIdx.x == 159) {
        // labels dtype probe: first 1200 int64 words == extent of an int32 buffer
        // of 2400 elems (never OOB). Real int64 labels all lie in [0,91).
        __shared__ int bad;
        if (threadIdx.x == 0) bad = 0;
        __syncthreads();
        for (int i = threadIdx.x; i < 1200; i += 256) {
            long long v = lab[i];
            if (v < 0 || v >= 91) bad = 1;
        }
        __syncthreads();
        if (threadIdx.x == 0) g_lab64 = bad ? 0 : 1;
    }
}

// ---------------------------------------------------------------- top-k: one warp per batch
__global__ void topk_kernel(const float* __restrict__ boxes,
                            const float* __restrict__ scores,
                            const void* __restrict__ labels_raw,
                            float* __restrict__ out) {
    int b = blockIdx.x;
    int t = threadIdx.x;
    int lab64 = g_lab64;
    const int*       l32 = (const int*)labels_raw;
    const long long* l64 = (const long long*)labels_raw;

    float v[10];
    #pragma unroll
    for (int r = 0; r < 10; r++) {
        int i = t + 32*r;
        float s = -INFINITY;
        if (i < NBOX) {
            long long l = lab64 ? l64[b*NBOX + i] : (long long)l32[b*NBOX + i];
            bool veh = (l==2)||(l==3)||(l==4)||(l==6)||(l==8);
            float sc = scores[b*NBOX + i];
            if (veh && sc > 0.8f) s = sc;
        }
        v[r] = s;
    }
    for (int k = 0; k < TOPK; k++) {
        float bv = -INFINITY; int bi = 0x7fffffff;
        #pragma unroll
        for (int r = 0; r < 10; r++) {
            int i = t + 32*r;
            if (v[r] > bv) { bv = v[r]; bi = i; }
        }
        #pragma unroll
        for (int o = 16; o > 0; o >>= 1) {
            float ov = __shfl_down_sync(0xffffffffu, bv, o);
            int   oi = __shfl_down_sync(0xffffffffu, bi, o);
            if (ov > bv || (ov == bv && oi < bi)) { bv = ov; bi = oi; }
        }
        bv = __shfl_sync(0xffffffffu, bv, 0);
        bi = __shfl_sync(0xffffffffu, bi, 0);
        bool valid = (bv != -INFINITY);
        if (valid && (bi & 31) == t) {
            int r = bi >> 5;
            #pragma unroll
            for (int rr = 0; rr < 10; rr++) if (rr == r) v[rr] = -INFINITY;
        }
        if (t == 0) {
            float b0=0.f,b1=0.f,b2=0.f,b3=0.f;
            if (valid) {
                const float* bp = boxes + (b*NBOX + bi)*4;
                b0=bp[0]; b1=bp[1]; b2=bp[2]; b3=bp[3];
            }
            int bk = b*TOPK + k;
            out[OBJ_OFF + bk*4+0] = b0;
            out[OBJ_OFF + bk*4+1] = b1;
            out[OBJ_OFF + bk*4+2] = b2;
            out[OBJ_OFF + bk*4+3] = b3;
            out[VALID_OFF + bk]   = valid ? 1.0f : 0.0f;
            if (valid && b2 > b0 && b3 > b1) {
                int pos = atomicAdd(&g_njobs, 1);
                g_job_box[pos*4+0]=b0; g_job_box[pos*4+1]=b1;
                g_job_box[pos*4+2]=b2; g_job_box[pos*4+3]=b3;
                g_job_b[pos]  = b;
                g_job_bk[pos] = bk;
            }
        }
    }
}

// ---------------------------------------------------------------- RoIAlign (normalized on the fly)
__global__ void sample_kernel(const float* __restrict__ x) {
    int j = blockIdx.x;
    if (j >= g_njobs) return;
    int b = g_job_b[j];
    float bx0 = g_job_box[j*4+0], by0 = g_job_box[j*4+1];
    float bx1 = g_job_box[j*4+2], by1 = g_job_box[j*4+3];
    for (int idx = threadIdx.x; idx < 3*CROPS*CROPS; idx += blockDim.x) {
        int c  = idx >> 12;
        int rem = idx & 4095;
        int yi = rem >> 6, xi = rem & 63;
        float ys = by0 + (yi + 0.5f)*(1.0f/CROPS)*(by1 - by0);
        float xs = bx0 + (xi + 0.5f)*(1.0f/CROPS)*(bx1 - bx0);
        float yf = floorf(ys), xf = floorf(xs);
        float wy = ys - yf,  wx = xs - xf;
        int y0 = min(max((int)yf, 0), HW-1); int y1 = min(y0+1, HW-1);
        int x0 = min(max((int)xf, 0), HW-1); int x1 = min(x0+1, HW-1);
        const float* img = x + ((long)b*3 + c)*HW*HW;
        float m = c_mean[c], is = c_istd[c];
        float Ia = (img[y0*HW + x0]-m)*is, Ib = (img[y0*HW + x1]-m)*is;
        float Ic = (img[y1*HW + x0]-m)*is, Id = (img[y1*HW + x1]-m)*is;
        g_crops[j*(3*CROPS*CROPS) + idx] =
            Ia*(1.f-wy)*(1.f-wx) + Ib*(1.f-wy)*wx + Ic*wy*(1.f-wx) + Id*wy*wx;
    }
}

// ---------------------------------------------------------------- fullframe conv via mma.sync tf32
// block = (ct, oy, b): D[128 oc, 128 px]; 8 warps = 4 oc-groups (32 oc) x 2 px-groups (64 px).
// B (im2col) staged in smem fragment-packed; A (weights) LDG.128 from g_Wfrag.
__global__ void __launch_bounds__(256, 2) conv_mma_kernel(const float* __restrict__ x,
                                                          const float* __restrict__ bc) {
    extern __shared__ float smB[];   // 20480 floats, fragment-packed
    int t = threadIdx.x;
    int w = t >> 5, lane = t & 31;
    int ocg = w & 3, pxg = w >> 2;
    int bx = blockIdx.x;
    int ct = bx & 1, tile = bx >> 1;
    int oy = tile & 127, b = tile >> 7;
    int c0 = ct*128;

    // ---- build B: im2col, fragment-packed. thread task: (s=it, npair=w, lane).
    // float4 = { v(px0,k), v(px0,k+4), v(px1,k), v(px1,k+4) }, px1 = px0+8.
    {
        int k0  = lane & 3;
        int px0 = w*16 + (lane >> 2);
        int iybase = 4*oy - 1;
        #pragma unroll 4
        for (int it = 0; it < 20; it++) {
            float v[4];
            #pragma unroll
            for (int e = 0; e < 4; e++) {
                int k  = it*8 + k0 + (e & 1)*4;
                int px = px0 + (e >> 1)*8;
                float val = 0.f;
                if (k < 147) {
                    int cin = k/49; int rr = k - cin*49;
                    int ky = rr/7;  int kx = rr - ky*7;
                    int iy = iybase + ky;
                    int ix = 4*px + kx - 1;
                    if ((unsigned)iy < 512u && (unsigned)ix < 512u)
                        val = (x[(((long)b*3 + cin)*512 + iy)*512 + ix] - c_mean[cin])*c_istd[cin];
                }
                v[e] = val;
            }
            float4* dst = (float4*)smB + (it*8 + w)*32 + lane;
            *dst = make_float4(v[0], v[1], v[2], v[3]);
        }
    }
    __syncthreads();

    // ---- mainloop: 20 k-steps
    float d[2][8][4];
    #pragma unroll
    for (int mt = 0; mt < 2; mt++)
        #pragma unroll
        for (int nt = 0; nt < 8; nt++)
            #pragma unroll
            for (int r = 0; r < 4; r++) d[mt][nt][r] = 0.f;

    const uint4* afrag = (const uint4*)g_Wfrag + ((ct*20)*8 + ocg*2)*32 + lane;
    const uint4* bfrag = (const uint4*)smB + (pxg*4)*32 + lane;
    #pragma unroll 2
    for (int s = 0; s < 20; s++) {
        uint4 a0 = afrag[(s*8)*32];        // m-tile 0
        uint4 a1 = afrag[(s*8 + 1)*32];    // m-tile 1
        uint4 b0 = bfrag[(s*8)*32];
        uint4 b1 = bfrag[(s*8 + 1)*32];
        uint4 b2 = bfrag[(s*8 + 2)*32];
        uint4 b3 = bfrag[(s*8 + 3)*32];
        const uint32_t* ap0 = (const uint32_t*)&a0;
        const uint32_t* ap1 = (const uint32_t*)&a1;
        mma_tf32(d[0][0], ap0, b0.x, b0.y);  mma_tf32(d[0][1], ap0, b0.z, b0.w);
        mma_tf32(d[0][2], ap0, b1.x, b1.y);  mma_tf32(d[0][3], ap0, b1.z, b1.w);
        mma_tf32(d[0][4], ap0, b2.x, b2.y);  mma_tf32(d[0][5], ap0, b2.z, b2.w);
        mma_tf32(d[0][6], ap0, b3.x, b3.y);  mma_tf32(d[0][7], ap0, b3.z, b3.w);
        mma_tf32(d[1][0], ap1, b0.x, b0.y);  mma_tf32(d[1][1], ap1, b0.z, b0.w);
        mma_tf32(d[1][2], ap1, b1.x, b1.y);  mma_tf32(d[1][3], ap1, b1.z, b1.w);
        mma_tf32(d[1][4], ap1, b2.x, b2.y);  mma_tf32(d[1][5], ap1, b2.z, b2.w);
        mma_tf32(d[1][6], ap1, b3.x, b3.y);  mma_tf32(d[1][7], ap1, b3.z, b3.w);
    }

    // ---- epilogue: bias + relu + pool over px, atomic accumulate
    #pragma unroll
    for (int mt = 0; mt < 2; mt++) {
        int oc_r0 = c0 + ocg*32 + mt*16 + (lane >> 2);
        float bias0 = bc[oc_r0];
        float bias1 = bc[oc_r0 + 8];
        float s0 = 0.f, s1 = 0.f;
        #pragma unroll
        for (int nt = 0; nt < 8; nt++) {
            s0 += fmaxf(d[mt][nt][0] + bias0, 0.f) + fmaxf(d[mt][nt][1] + bias0, 0.f);
            s1 += fmaxf(d[mt][nt][2] + bias1, 0.f) + fmaxf(d[mt][nt][3] + bias1, 0.f);
        }
        s0 += __shfl_xor_sync(0xffffffffu, s0, 1);
        s0 += __shfl_xor_sync(0xffffffffu, s0, 2);
        s1 += __shfl_xor_sync(0xffffffffu, s1, 1);
        s1 += __shfl_xor_sync(0xffffffffu, s1, 2);
        if ((lane & 3) == 0) {
            atomicAdd(&g_pooled_full[b*OC + oc_r0],     s0);
            atomicAdd(&g_pooled_full[b*OC + oc_r0 + 8], s1);
        }
    }
}

// ---------------------------------------------------------------- crop conv+ReLU+pool (scalar FFMA2, exact fp32)
__global__ void __launch_bounds__(256, 2) conv_crop_kernel(const float* __restrict__ bc) {
    extern __shared__ float sm[];
    int t = threadIdx.x;
    int pxg = t & 31, cg = t >> 5;
    int cx2 = blockIdx.x;
    int ct = cx2 & 1; int half = (cx2 >> 1) & 1; int j = cx2 >> 2;
    if (j >= g_njobs) return;
    int c0 = ct*128;
    const float* crop = g_crops + (long)j*(3*CROPS*CROPS);
    int iy0 = half*32 - 1;
    for (int s = t; s < 105*67; s += 256) {
        int row = s / 67; int p = s - row*67;
        int cin = row / 35; int iyl = row - cin*35;
        int cy = iy0 + iyl, cxx = p - 1;
        float v = 0.f;
        if ((unsigned)cy < 64u && (unsigned)cxx < 64u)
            v = crop[(cin*64 + cy)*64 + cxx];
        sm[row*84 + (p&3)*18 + (p>>2)] = v;
    }
    __syncthreads();

    int rowoff[4];
    #pragma unroll
    for (int m = 0; m < 4; m++) {
        int px = pxg + 32*m;
        rowoff[m] = (px >> 4)*4*84 + (px & 15);
    }
    u64 acc[4][8];
    {
        const u64* b2 = (const u64*)(bc + c0 + cg*16);
        #pragma unroll
        for (int i = 0; i < 8; i++) {
            u64 bb = b2[i];
            acc[0][i]=bb; acc[1][i]=bb; acc[2][i]=bb; acc[3][i]=bb;
        }
    }
    const float* wbase = g_Wt + c0 + cg*16;
    for (int cin = 0; cin < 3; cin++) {
        const float* plc = sm + cin*35*84;
        const float* wc  = wbase + cin*49*OC;
        #pragma unroll
        for (int ky = 0; ky < 7; ky++) {
            #pragma unroll
            for (int kx = 0; kx < 7; kx++) {
                const float* pl = plc + ky*84 + (kx&3)*18 + (kx>>2);
                float a0 = pl[rowoff[0]], a1 = pl[rowoff[1]];
                float a2 = pl[rowoff[2]], a3 = pl[rowoff[3]];
                const ulonglong2* wp = (const ulonglong2*)(wc + (ky*7+kx)*OC);
                ulonglong2 wA = wp[0], wB = wp[1], wC = wp[2], wD = wp[3];
                u64 dd;
                dd = dup2(a0);
                ffma2(acc[0][0],dd,wA.x); ffma2(acc[0][1],dd,wA.y); ffma2(acc[0][2],dd,wB.x); ffma2(acc[0][3],dd,wB.y);
                ffma2(acc[0][4],dd,wC.x); ffma2(acc[0][5],dd,wC.y); ffma2(acc[0][6],dd,wD.x); ffma2(acc[0][7],dd,wD.y);
                dd = dup2(a1);
                ffma2(acc[1][0],dd,wA.x); ffma2(acc[1][1],dd,wA.y); ffma2(acc[1][2],dd,wB.x); ffma2(acc[1][3],dd,wB.y);
                ffma2(acc[1][4],dd,wC.x); ffma2(acc[1][5],dd,wC.y); ffma2(acc[1][6],dd,wD.x); ffma2(acc[1][7],dd,wD.y);
                dd = dup2(a2);
                ffma2(acc[2][0],dd,wA.x); ffma2(acc[2][1],dd,wA.y); ffma2(acc[2][2],dd,wB.x); ffma2(acc[2][3],dd,wB.y);
                ffma2(acc[2][4],dd,wC.x); ffma2(acc[2][5],dd,wC.y); ffma2(acc[2][6],dd,wD.x); ffma2(acc[2][7],dd,wD.y);
                dd = dup2(a3);
                ffma2(acc[3][0],dd,wA.x); ffma2(acc[3][1],dd,wA.y); ffma2(acc[3][2],dd,wB.x); ffma2(acc[3][3],dd,wB.y);
                ffma2(acc[3][4],dd,wC.x); ffma2(acc[3][5],dd,wC.y); ffma2(acc[3][6],dd,wD.x); ffma2(acc[3][7],dd,wD.y);
            }
        }
    }
    #pragma unroll
    for (int i = 0; i < 8; i++) {
        float s0 = 0.f, s1 = 0.f;
        #pragma unroll
        for (int m = 0; m < 4; m++) {
            float lo, hi; unpack2(acc[m][i], lo, hi);
            s0 += fmaxf(lo, 0.f); s1 += fmaxf(hi, 0.f);
        }
        #pragma unroll
        for (int o = 16; o > 0; o >>= 1) {
            s0 += __shfl_down_sync(0xffffffffu, s0, o);
            s1 += __shfl_down_sync(0xffffffffu, s1, o);
        }
        if (pxg == 0) {
            atomicAdd(&g_pooled_crop[j*OC + c0 + cg*16 + 2*i],     s0);
            atomicAdd(&g_pooled_crop[j*OC + c0 + cg*16 + 2*i + 1], s1);
        }
    }
}

// ---------------------------------------------------------------- unified FC
__global__ void __launch_bounds__(256) fc_kernel(const float* __restrict__ Wf,
                                                 const float* __restrict__ bf,
                                                 float* __restrict__ out) {
    int y = blockIdx.y, t = threadIdx.x;
    int o = blockIdx.x*256 + t;
    __shared__ float sp[8*OC];
    if (y == 0) {
        for (int s = t; s < BATCH*OC; s += 256)
            sp[s] = g_pooled_full[s] * (1.0f/16384.0f);
        __syncthreads();
        float acc[8] = {0.f,0.f,0.f,0.f,0.f,0.f,0.f,0.f};
        for (int c = 0; c < OC; c++) {
            float w = Wf[(long)c*FCO + o];
            #pragma unroll
            for (int b2 = 0; b2 < 8; b2++) acc[b2] += sp[b2*OC + c] * w;
        }
        float bias = bf[o];
        #pragma unroll
        for (int b2 = 0; b2 < 8; b2++)
            out[FULL_OFF + b2*FCO + o] = acc[b2] + bias;
    } else {
        int nj = g_njobs;
        int j0 = (y - 1)*8;
        if (j0 >= nj) return;
        for (int s = t; s < 8*OC; s += 256) {
            int jj = s >> 8; int c = s & 255;
            int j = j0 + jj;
            sp[s] = (j < nj) ? g_pooled_crop[j*OC + c] * (1.0f/256.0f) : 0.f;
        }
        __syncthreads();
        float acc[8] = {0.f,0.f,0.f,0.f,0.f,0.f,0.f,0.f};
        for (int c = 0; c < OC; c++) {
            float w = Wf[(long)c*FCO + o];
            #pragma unroll
            for (int jj = 0; jj < 8; jj++) acc[jj] += sp[jj*OC + c] * w;
        }
        float bias = bf[o];
        #pragma unroll
        for (int jj = 0; jj < 8; jj++) {
            int j = j0 + jj;
            if (j < nj)
                out[FEAT_OFF + (long)g_job_bk[j]*FCO + o] = acc[jj] + bias;
        }
    }
}

// ---------------------------------------------------------------- launch
extern "C" void kernel_launch(void* const* d_in, const int* in_sizes, int n_in,
                              void* d_out, int out_size) {
    const float* x      = (const float*)d_in[0];
    const float* boxes  = (const float*)d_in[1];
    const float* scores = (const float*)d_in[2];
    const void*  labels = d_in[3];
    const float* Wc     = (const float*)d_in[4];
    const float* bc     = (const float*)d_in[5];
    const float* Wf     = (const float*)d_in[6];
    const float* bf     = (const float*)d_in[7];
    float* out = (float*)d_out;

    cudaFuncSetAttribute(conv_mma_kernel, cudaFuncAttributeMaxDynamicSharedMemorySize,
                         BSMEM_FLOATS*4);

    prep_kernel<<<160, 256>>>(Wc, (const long long*)labels);
    topk_kernel<<<BATCH, 32>>>(boxes, scores, labels, out);
    cudaMemsetAsync(out + FEAT_OFF, 0, (size_t)BATCH*TOPK*FCO*sizeof(float));
    sample_kernel<<<BATCH*TOPK, 256>>>(x);
    conv_mma_kernel<<<2048, 256, BSMEM_FLOATS*4>>>(x, bc);
    conv_crop_kernel<<<CROP_BLOCKS, 256, CROP_SMEM>>>(bc);
    fc_kernel<<<dim3(16, 21), 256>>>(Wf, bf, out);
}

// round 8
// speedup vs baseline: 2.5351x; 1.0202x over previous
#include <cuda_runtime.h>
#include <math.h>
#include <stdint.h>

typedef unsigned long long u64;

#define BATCH 8
#define NBOX  300
#define TOPK  20
#define HW    512
#define CROPS 64
#define OC    256
#define FCO   4096

// d_out layout (floats): Objects[8,20,4] | Object_features[8,20,4096] | valid[8,20] | fullframe[8,4096]
#define OBJ_OFF   0
#define FEAT_OFF  640
#define VALID_OFF 656000
#define FULL_OFF  656160

#define KSTEPS 19                      // 147 -> 152 (19 k-steps of 8)
#define NFRAG  (KSTEPS*8*32*4)         // 19456 floats per ct
#define BSMEM_BYTES (KSTEPS*8*32*16)   // 77824 B fragment-packed im2col
#define DEC_OFF  BSMEM_BYTES           // int4[152] decode table
#define CONV_SMEM (BSMEM_BYTES + 152*16)   // 80256 B
#define FULL_BLOCKS 2048
#define CROP_BLOCKS (BATCH*TOPK*4)     // job * 2 halves * 2 ct

__constant__ float c_mean[3] = {0.485f, 0.456f, 0.406f};
__constant__ float c_istd[3] = {1.0f/0.229f, 1.0f/0.224f, 1.0f/0.225f};

__device__ float g_pooled_full[BATCH*OC];
__device__ float g_pooled_crop[BATCH*TOPK*OC];
__device__ float g_crops[BATCH*TOPK*3*CROPS*CROPS];
__device__ __align__(16) float g_Wt[147*OC];         // [k][oc] for scalar crop conv
__device__ __align__(16) float g_WfragHi[2*NFRAG];   // tf32-hi weight fragments
__device__ __align__(16) float g_WfragLo[2*NFRAG];   // tf32-lo weight fragments
__device__ float g_job_box[BATCH*TOPK*4];
__device__ int   g_job_b[BATCH*TOPK];
__device__ int   g_job_bk[BATCH*TOPK];
__device__ int   g_njobs;
__device__ int   g_lab64;

// ---------------------------------------------------------------- helpers
__device__ __forceinline__ void ffma2(u64 &d, u64 a, u64 b) {
    asm("fma.rn.f32x2 %0, %1, %2, %0;" : "+l"(d) : "l"(a), "l"(b));
}
__device__ __forceinline__ u64 dup2(float a) {
    u64 r; asm("mov.b64 %0, {%1, %1};" : "=l"(r) : "f"(a)); return r;
}
__device__ __forceinline__ void unpack2(u64 v, float &lo, float &hi) {
    asm("mov.b64 {%0, %1}, %2;" : "=f"(lo), "=f"(hi) : "l"(v));
}
__device__ __forceinline__ float tf32r(float a) {
    uint32_t u; asm("cvt.rna.tf32.f32 %0, %1;" : "=r"(u) : "f"(a));
    return __uint_as_float(u);
}
__device__ __forceinline__ void mma_tf32(float* d, const uint32_t* a, uint32_t b0, uint32_t b1) {
    asm volatile(
        "mma.sync.aligned.m16n8k8.row.col.f32.tf32.tf32.f32 "
        "{%0,%1,%2,%3}, {%4,%5,%6,%7}, {%8,%9}, {%0,%1,%2,%3};"
        : "+f"(d[0]), "+f"(d[1]), "+f"(d[2]), "+f"(d[3])
        : "r"(a[0]), "r"(a[1]), "r"(a[2]), "r"(a[3]), "r"(b0), "r"(b1));
}

// ---------------------------------------------------------------- prep
__global__ void prep_kernel(const float* __restrict__ Wc,
                            const long long* __restrict__ lab) {
    int gid = blockIdx.x*256 + threadIdx.x;     // 0..40959
    if (gid < BATCH*OC)      g_pooled_full[gid] = 0.f;
    if (gid < BATCH*TOPK*OC) g_pooled_crop[gid] = 0.f;
    if (gid == 0)            g_njobs = 0;
    if (blockIdx.x < 147) {
        int k = blockIdx.x, c = threadIdx.x;
        g_Wt[k*OC + c] = Wc[c*147 + k];
    }
    // hi/lo tf32 weight fragments: idx = (((ct*19+s)*8+Ml)*32+lane)*4+reg
    if (gid < 2*NFRAG) {
        int reg  = gid & 3;
        int lane = (gid >> 2) & 31;
        int Ml   = (gid >> 7) & 7;
        int ct   = gid / NFRAG;
        int s    = (gid - ct*NFRAG) >> 10;
        int oc = ct*128 + Ml*16 + (lane >> 2) + (reg & 1)*8;
        int k  = s*8 + (lane & 3) + (reg >> 1)*4;
        float wv = (k < 147) ? Wc[oc*147 + k] : 0.f;
        float hi = tf32r(wv);
        g_WfragHi[gid] = hi;
        g_WfragLo[gid] = tf32r(wv - hi);
    }
    if (blockIdx.x == 159) {
        // labels dtype probe: first 1200 int64 words == extent of an int32 buffer
        // of 2400 elems (never OOB). Real int64 labels all lie in [0,91).
        __shared__ int bad;
        if (threadIdx.x == 0) bad = 0;
        __syncthreads();
        for (int i = threadIdx.x; i < 1200; i += 256) {
            long long v = lab[i];
            if (v < 0 || v >= 91) bad = 1;
        }
        __syncthreads();
        if (threadIdx.x == 0) g_lab64 = bad ? 0 : 1;
    }
}

// ---------------------------------------------------------------- top-k: one warp per batch
__global__ void topk_kernel(const float* __restrict__ boxes,
                            const float* __restrict__ scores,
                            const void* __restrict__ labels_raw,
                            float* __restrict__ out) {
    int b = blockIdx.x;
    int t = threadIdx.x;
    int lab64 = g_lab64;
    const int*       l32 = (const int*)labels_raw;
    const long long* l64 = (const long long*)labels_raw;

    float v[10];
    #pragma unroll
    for (int r = 0; r < 10; r++) {
        int i = t + 32*r;
        float s = -INFINITY;
        if (i < NBOX) {
            long long l = lab64 ? l64[b*NBOX + i] : (long long)l32[b*NBOX + i];
            bool veh = (l==2)||(l==3)||(l==4)||(l==6)||(l==8);
            float sc = scores[b*NBOX + i];
            if (veh && sc > 0.8f) s = sc;
        }
        v[r] = s;
    }
    for (int k = 0; k < TOPK; k++) {
        float bv = -INFINITY; int bi = 0x7fffffff;
        #pragma unroll
        for (int r = 0; r < 10; r++) {
            int i = t + 32*r;
            if (v[r] > bv) { bv = v[r]; bi = i; }
        }
        #pragma unroll
        for (int o = 16; o > 0; o >>= 1) {
            float ov = __shfl_down_sync(0xffffffffu, bv, o);
            int   oi = __shfl_down_sync(0xffffffffu, bi, o);
            if (ov > bv || (ov == bv && oi < bi)) { bv = ov; bi = oi; }
        }
        bv = __shfl_sync(0xffffffffu, bv, 0);
        bi = __shfl_sync(0xffffffffu, bi, 0);
        bool valid = (bv != -INFINITY);
        if (valid && (bi & 31) == t) {
            int r = bi >> 5;
            #pragma unroll
            for (int rr = 0; rr < 10; rr++) if (rr == r) v[rr] = -INFINITY;
        }
        if (t == 0) {
            float b0=0.f,b1=0.f,b2=0.f,b3=0.f;
            if (valid) {
                const float* bp = boxes + (b*NBOX + bi)*4;
                b0=bp[0]; b1=bp[1]; b2=bp[2]; b3=bp[3];
            }
            int bk = b*TOPK + k;
            out[OBJ_OFF + bk*4+0] = b0;
            out[OBJ_OFF + bk*4+1] = b1;
            out[OBJ_OFF + bk*4+2] = b2;
            out[OBJ_OFF + bk*4+3] = b3;
            out[VALID_OFF + bk]   = valid ? 1.0f : 0.0f;
            if (valid && b2 > b0 && b3 > b1) {
                int pos = atomicAdd(&g_njobs, 1);
                g_job_box[pos*4+0]=b0; g_job_box[pos*4+1]=b1;
                g_job_box[pos*4+2]=b2; g_job_box[pos*4+3]=b3;
                g_job_b[pos]  = b;
                g_job_bk[pos] = bk;
            }
        }
    }
}

// ---------------------------------------------------------------- RoIAlign (normalized on the fly)
__global__ void sample_kernel(const float* __restrict__ x) {
    int j = blockIdx.x;
    if (j >= g_njobs) return;
    int b = g_job_b[j];
    float bx0 = g_job_box[j*4+0], by0 = g_job_box[j*4+1];
    float bx1 = g_job_box[j*4+2], by1 = g_job_box[j*4+3];
    for (int idx = threadIdx.x; idx < 3*CROPS*CROPS; idx += blockDim.x) {
        int c  = idx >> 12;
        int rem = idx & 4095;
        int yi = rem >> 6, xi = rem & 63;
        float ys = by0 + (yi + 0.5f)*(1.0f/CROPS)*(by1 - by0);
        float xs = bx0 + (xi + 0.5f)*(1.0f/CROPS)*(bx1 - bx0);
        float yf = floorf(ys), xf = floorf(xs);
        float wy = ys - yf,  wx = xs - xf;
        int y0 = min(max((int)yf, 0), HW-1); int y1 = min(y0+1, HW-1);
        int x0 = min(max((int)xf, 0), HW-1); int x1 = min(x0+1, HW-1);
        const float* img = x + ((long)b*3 + c)*HW*HW;
        float m = c_mean[c], is = c_istd[c];
        float Ia = (img[y0*HW + x0]-m)*is, Ib = (img[y0*HW + x1]-m)*is;
        float Ic = (img[y1*HW + x0]-m)*is, Id = (img[y1*HW + x1]-m)*is;
        g_crops[j*(3*CROPS*CROPS) + idx] =
            Ia*(1.f-wy)*(1.f-wx) + Ib*(1.f-wy)*wx + Ic*wy*(1.f-wx) + Id*wy*wx;
    }
}

// ---------------------------------------------------------------- unified conv
// bx < FULL_BLOCKS: tf32 mma fullframe tile (128 oc x 128 px), weights hi+lo split.
// else: scalar FFMA2 crop tile (exact fp32).
__global__ void __launch_bounds__(256, 2) conv_kernel(const float* __restrict__ x,
                                                      const float* __restrict__ bc) {
    extern __shared__ char smc[];
    int t = threadIdx.x;
    int w = t >> 5, lane = t & 31;
    int bx = blockIdx.x;

    if (bx < FULL_BLOCKS) {
        float* smB = (float*)smc;
        int4*  dec = (int4*)(smc + DEC_OFF);
        int ocg = w & 3, pxg = w >> 2;
        int ct = bx & 1, tile = bx >> 1;
        int oy = tile & 127, b = tile >> 7;
        int c0 = ct*128;

        // decode table: k -> {row_off (cin*2^18 + ky*512 + kx - 1), ky, kx, cin}
        if (t < 152) {
            int k = t;
            int cin = k/49; int rr = k - cin*49;
            int ky = rr/7;  int kx = rr - ky*7;
            if (k >= 147) { cin = 0; ky = 0; kx = 0; }
            dec[t] = make_int4(cin*262144 + ky*512 + kx - 1, ky, kx, cin);
        }
        __syncthreads();

        // build fragment-packed im2col (rna-rounded to tf32)
        {
            int k0  = lane & 3;
            int px0 = w*16 + (lane >> 2);
            int iyb = 4*oy - 1;
            int iyb512 = iyb*512;
            const float* xb = x + (long)b*3*262144;
            #pragma unroll 4
            for (int it = 0; it < KSTEPS; it++) {
                float v[4];
                #pragma unroll
                for (int e = 0; e < 4; e++) {
                    int k  = it*8 + k0 + (e & 1)*4;
                    int px = px0 + (e >> 1)*8;
                    float val = 0.f;
                    if (k < 147) {
                        int4 dc = dec[k];
                        int iy = iyb + dc.y;
                        int ix = 4*px - 1 + dc.z;
                        if ((unsigned)iy < 512u && (unsigned)ix < 512u)
                            val = (xb[dc.x + iyb512 + 4*px] - c_mean[dc.w])*c_istd[dc.w];
                    }
                    v[e] = tf32r(val);
                }
                float4* dst = (float4*)smB + (it*8 + w)*32 + lane;
                *dst = make_float4(v[0], v[1], v[2], v[3]);
            }
        }
        __syncthreads();

        float d[2][8][4];
        #pragma unroll
        for (int mt = 0; mt < 2; mt++)
            #pragma unroll
            for (int nt = 0; nt < 8; nt++)
                #pragma unroll
                for (int r = 0; r < 4; r++) d[mt][nt][r] = 0.f;

        const uint4* aH = (const uint4*)g_WfragHi + ((ct*KSTEPS)*8 + ocg*2)*32 + lane;
        const uint4* aL = (const uint4*)g_WfragLo + ((ct*KSTEPS)*8 + ocg*2)*32 + lane;
        const uint4* bf = (const uint4*)smB + (pxg*4)*32 + lane;
        #pragma unroll 1
        for (int s = 0; s < KSTEPS; s++) {
            uint4 h0 = aH[(s*8)*32];
            uint4 h1 = aH[(s*8 + 1)*32];
            uint4 l0 = aL[(s*8)*32];
            uint4 l1 = aL[(s*8 + 1)*32];
            uint4 b0 = bf[(s*8)*32];
            uint4 b1 = bf[(s*8 + 1)*32];
            uint4 b2 = bf[(s*8 + 2)*32];
            uint4 b3 = bf[(s*8 + 3)*32];
            const uint32_t* ph0 = (const uint32_t*)&h0;
            const uint32_t* ph1 = (const uint32_t*)&h1;
            const uint32_t* pl0 = (const uint32_t*)&l0;
            const uint32_t* pl1 = (const uint32_t*)&l1;
            mma_tf32(d[0][0], ph0, b0.x, b0.y);  mma_tf32(d[0][0], pl0, b0.x, b0.y);
            mma_tf32(d[0][1], ph0, b0.z, b0.w);  mma_tf32(d[0][1], pl0, b0.z, b0.w);
            mma_tf32(d[0][2], ph0, b1.x, b1.y);  mma_tf32(d[0][2], pl0, b1.x, b1.y);
            mma_tf32(d[0][3], ph0, b1.z, b1.w);  mma_tf32(d[0][3], pl0, b1.z, b1.w);
            mma_tf32(d[0][4], ph0, b2.x, b2.y);  mma_tf32(d[0][4], pl0, b2.x, b2.y);
            mma_tf32(d[0][5], ph0, b2.z, b2.w);  mma_tf32(d[0][5], pl0, b2.z, b2.w);
            mma_tf32(d[0][6], ph0, b3.x, b3.y);  mma_tf32(d[0][6], pl0, b3.x, b3.y);
            mma_tf32(d[0][7], ph0, b3.z, b3.w);  mma_tf32(d[0][7], pl0, b3.z, b3.w);
            mma_tf32(d[1][0], ph1, b0.x, b0.y);  mma_tf32(d[1][0], pl1, b0.x, b0.y);
            mma_tf32(d[1][1], ph1, b0.z, b0.w);  mma_tf32(d[1][1], pl1, b0.z, b0.w);
            mma_tf32(d[1][2], ph1, b1.x, b1.y);  mma_tf32(d[1][2], pl1, b1.x, b1.y);
            mma_tf32(d[1][3], ph1, b1.z, b1.w);  mma_tf32(d[1][3], pl1, b1.z, b1.w);
            mma_tf32(d[1][4], ph1, b2.x, b2.y);  mma_tf32(d[1][4], pl1, b2.x, b2.y);
            mma_tf32(d[1][5], ph1, b2.z, b2.w);  mma_tf32(d[1][5], pl1, b2.z, b2.w);
            mma_tf32(d[1][6], ph1, b3.x, b3.y);  mma_tf32(d[1][6], pl1, b3.x, b3.y);
            mma_tf32(d[1][7], ph1, b3.z, b3.w);  mma_tf32(d[1][7], pl1, b3.z, b3.w);
        }

        // epilogue: bias + relu + pool over px, atomic accumulate
        #pragma unroll
        for (int mt = 0; mt < 2; mt++) {
            int oc_r0 = c0 + ocg*32 + mt*16 + (lane >> 2);
            float bias0 = bc[oc_r0];
            float bias1 = bc[oc_r0 + 8];
            float s0 = 0.f, s1 = 0.f;
            #pragma unroll
            for (int nt = 0; nt < 8; nt++) {
                s0 += fmaxf(d[mt][nt][0] + bias0, 0.f) + fmaxf(d[mt][nt][1] + bias0, 0.f);
                s1 += fmaxf(d[mt][nt][2] + bias1, 0.f) + fmaxf(d[mt][nt][3] + bias1, 0.f);
            }
            s0 += __shfl_xor_sync(0xffffffffu, s0, 1);
            s0 += __shfl_xor_sync(0xffffffffu, s0, 2);
            s1 += __shfl_xor_sync(0xffffffffu, s1, 1);
            s1 += __shfl_xor_sync(0xffffffffu, s1, 2);
            if ((lane & 3) == 0) {
                atomicAdd(&g_pooled_full[b*OC + oc_r0],     s0);
                atomicAdd(&g_pooled_full[b*OC + oc_r0 + 8], s1);
            }
        }
    } else {
        // ------------- crop: half (8 out-rows = 128 px) x 128 channels, exact fp32
        float* sm = (float*)smc;
        int pxg = lane, cg = w;
        int cx2 = bx - FULL_BLOCKS;
        int ct = cx2 & 1; int half = (cx2 >> 1) & 1; int j = cx2 >> 2;
        if (j >= g_njobs) return;
        int c0 = ct*128;
        const float* crop = g_crops + (long)j*(3*CROPS*CROPS);
        int iy0 = half*32 - 1;
        for (int s = t; s < 105*67; s += 256) {
            int row = s / 67; int p = s - row*67;
            int cin = row / 35; int iyl = row - cin*35;
            int cy = iy0 + iyl, cxx = p - 1;
            float v = 0.f;
            if ((unsigned)cy < 64u && (unsigned)cxx < 64u)
                v = crop[(cin*64 + cy)*64 + cxx];
            sm[row*84 + (p&3)*18 + (p>>2)] = v;
        }
        __syncthreads();

        int rowoff[4];
        #pragma unroll
        for (int m = 0; m < 4; m++) {
            int px = pxg + 32*m;
            rowoff[m] = (px >> 4)*4*84 + (px & 15);
        }
        u64 acc[4][8];
        {
            const u64* b2 = (const u64*)(bc + c0 + cg*16);
            #pragma unroll
            for (int i = 0; i < 8; i++) {
                u64 bb = b2[i];
                acc[0][i]=bb; acc[1][i]=bb; acc[2][i]=bb; acc[3][i]=bb;
            }
        }
        const float* wbase = g_Wt + c0 + cg*16;
        for (int cin = 0; cin < 3; cin++) {
            const float* plc = sm + cin*35*84;
            const float* wc  = wbase + cin*49*OC;
            #pragma unroll
            for (int ky = 0; ky < 7; ky++) {
                #pragma unroll
                for (int kx = 0; kx < 7; kx++) {
                    const float* pl = plc + ky*84 + (kx&3)*18 + (kx>>2);
                    float a0 = pl[rowoff[0]], a1 = pl[rowoff[1]];
                    float a2 = pl[rowoff[2]], a3 = pl[rowoff[3]];
                    const ulonglong2* wp = (const ulonglong2*)(wc + (ky*7+kx)*OC);
                    ulonglong2 wA = wp[0], wB = wp[1], wC = wp[2], wD = wp[3];
                    u64 dd;
                    dd = dup2(a0);
                    ffma2(acc[0][0],dd,wA.x); ffma2(acc[0][1],dd,wA.y); ffma2(acc[0][2],dd,wB.x); ffma2(acc[0][3],dd,wB.y);
                    ffma2(acc[0][4],dd,wC.x); ffma2(acc[0][5],dd,wC.y); ffma2(acc[0][6],dd,wD.x); ffma2(acc[0][7],dd,wD.y);
                    dd = dup2(a1);
                    ffma2(acc[1][0],dd,wA.x); ffma2(acc[1][1],dd,wA.y); ffma2(acc[1][2],dd,wB.x); ffma2(acc[1][3],dd,wB.y);
                    ffma2(acc[1][4],dd,wC.x); ffma2(acc[1][5],dd,wC.y); ffma2(acc[1][6],dd,wD.x); ffma2(acc[1][7],dd,wD.y);
                    dd = dup2(a2);
                    ffma2(acc[2][0],dd,wA.x); ffma2(acc[2][1],dd,wA.y); ffma2(acc[2][2],dd,wB.x); ffma2(acc[2][3],dd,wB.y);
                    ffma2(acc[2][4],dd,wC.x); ffma2(acc[2][5],dd,wC.y); ffma2(acc[2][6],dd,wD.x); ffma2(acc[2][7],dd,wD.y);
                    dd = dup2(a3);
                    ffma2(acc[3][0],dd,wA.x); ffma2(acc[3][1],dd,wA.y); ffma2(acc[3][2],dd,wB.x); ffma2(acc[3][3],dd,wB.y);
                    ffma2(acc[3][4],dd,wC.x); ffma2(acc[3][5],dd,wC.y); ffma2(acc[3][6],dd,wD.x); ffma2(acc[3][7],dd,wD.y);
                }
            }
        }
        #pragma unroll
        for (int i = 0; i < 8; i++) {
            float s0 = 0.f, s1 = 0.f;
            #pragma unroll
            for (int m = 0; m < 4; m++) {
                float lo, hi; unpack2(acc[m][i], lo, hi);
                s0 += fmaxf(lo, 0.f); s1 += fmaxf(hi, 0.f);
            }
            #pragma unroll
            for (int o = 16; o > 0; o >>= 1) {
                s0 += __shfl_down_sync(0xffffffffu, s0, o);
                s1 += __shfl_down_sync(0xffffffffu, s1, o);
            }
            if (pxg == 0) {
                atomicAdd(&g_pooled_crop[j*OC + c0 + cg*16 + 2*i],     s0);
                atomicAdd(&g_pooled_crop[j*OC + c0 + cg*16 + 2*i + 1], s1);
            }
        }
    }
}

// ---------------------------------------------------------------- unified FC
__global__ void __launch_bounds__(256) fc_kernel(const float* __restrict__ Wf,
                                                 const float* __restrict__ bf,
                                                 float* __restrict__ out) {
    int y = blockIdx.y, t = threadIdx.x;
    int o = blockIdx.x*256 + t;
    __shared__ float sp[8*OC];
    if (y == 0) {
        for (int s = t; s < BATCH*OC; s += 256)
            sp[s] = g_pooled_full[s] * (1.0f/16384.0f);
        __syncthreads();
        float acc[8] = {0.f,0.f,0.f,0.f,0.f,0.f,0.f,0.f};
        for (int c = 0; c < OC; c++) {
            float w = Wf[(long)c*FCO + o];
            #pragma unroll
            for (int b2 = 0; b2 < 8; b2++) acc[b2] += sp[b2*OC + c] * w;
        }
        float bias = bf[o];
        #pragma unroll
        for (int b2 = 0; b2 < 8; b2++)
            out[FULL_OFF + b2*FCO + o] = acc[b2] + bias;
    } else {
        int nj = g_njobs;
        int j0 = (y - 1)*8;
        if (j0 >= nj) return;
        for (int s = t; s < 8*OC; s += 256) {
            int jj = s >> 8; int c = s & 255;
            int j = j0 + jj;
            sp[s] = (j < nj) ? g_pooled_crop[j*OC + c] * (1.0f/256.0f) : 0.f;
        }
        __syncthreads();
        float acc[8] = {0.f,0.f,0.f,0.f,0.f,0.f,0.f,0.f};
        for (int c = 0; c < OC; c++) {
            float w = Wf[(long)c*FCO + o];
            #pragma unroll
            for (int jj = 0; jj < 8; jj++) acc[jj] += sp[jj*OC + c] * w;
        }
        float bias = bf[o];
        #pragma unroll
        for (int jj = 0; jj < 8; jj++) {
            int j = j0 + jj;
            if (j < nj)
                out[FEAT_OFF + (long)g_job_bk[j]*FCO + o] = acc[jj] + bias;
        }
    }
}

// ---------------------------------------------------------------- launch
extern "C" void kernel_launch(void* const* d_in, const int* in_sizes, int n_in,
                              void* d_out, int out_size) {
    const float* x      = (const float*)d_in[0];
    const float* boxes  = (const float*)d_in[1];
    const float* scores = (const float*)d_in[2];
    const void*  labels = d_in[3];
    const float* Wc     = (const float*)d_in[4];
    const float* bc     = (const float*)d_in[5];
    const float* Wf     = (const float*)d_in[6];
    const float* bf     = (const float*)d_in[7];
    float* out = (float*)d_out;

    cudaFuncSetAttribute(conv_kernel, cudaFuncAttributeMaxDynamicSharedMemorySize, CONV_SMEM);

    prep_kernel<<<320, 256>>>(Wc, (const long long*)labels);
    topk_kernel<<<BATCH, 32>>>(boxes, scores, labels, out);
    cudaMemsetAsync(out + FEAT_OFF, 0, (size_t)BATCH*TOPK*FCO*sizeof(float));
    sample_kernel<<<BATCH*TOPK, 256>>>(x);
    conv_kernel<<<FULL_BLOCKS + CROP_BLOCKS, 256, CONV_SMEM>>>(x, bc);
    fc_kernel<<<dim3(16, 21), 256>>>(Wf, bf, out);
}

// round 9
// speedup vs baseline: 2.5620x; 1.0106x over previous
#include <cuda_runtime.h>
#include <math.h>
#include <stdint.h>

typedef unsigned long long u64;

#define BATCH 8
#define NBOX  300
#define TOPK  20
#define HW    512
#define CROPS 64
#define OC    256
#define FCO   4096

// d_out layout (floats): Objects[8,20,4] | Object_features[8,20,4096] | valid[8,20] | fullframe[8,4096]
#define OBJ_OFF   0
#define FEAT_OFF  640
#define VALID_OFF 656000
#define FULL_OFF  656160

#define KSTEPS 19                      // 147 -> 152 (19 k-steps of 8)
#define NFRAG  (KSTEPS*8*32*4)         // 19456 floats per ct
#define BSMEM_BYTES (KSTEPS*8*32*16)   // 77824 B fragment-packed im2col
#define DEC_OFF  BSMEM_BYTES           // int4[152] decode table
#define CONV_SMEM (BSMEM_BYTES + 152*16)   // 80256 B
#define FULL_BLOCKS 2048
#define CROP_BLOCKS (BATCH*TOPK*4)     // job * 2 halves * 2 ct

__constant__ float c_mean[3] = {0.485f, 0.456f, 0.406f};
__constant__ float c_istd[3] = {1.0f/0.229f, 1.0f/0.224f, 1.0f/0.225f};

__device__ float g_pooled_full[BATCH*OC];
__device__ float g_pooled_crop[BATCH*TOPK*OC];
__device__ float g_crops[BATCH*TOPK*3*CROPS*CROPS];
__device__ __align__(16) float g_Wt[147*OC];         // [k][oc] for scalar crop conv
__device__ __align__(16) float g_WfragHi[2*NFRAG];   // tf32-hi weight fragments
__device__ __align__(16) float g_WfragLo[2*NFRAG];   // tf32-lo weight fragments
__device__ float g_job_box[BATCH*TOPK*4];
__device__ int   g_job_b[BATCH*TOPK];
__device__ int   g_job_bk[BATCH*TOPK];
__device__ int   g_njobs;
__device__ int   g_lab64;

// ---------------------------------------------------------------- helpers
__device__ __forceinline__ void ffma2(u64 &d, u64 a, u64 b) {
    asm("fma.rn.f32x2 %0, %1, %2, %0;" : "+l"(d) : "l"(a), "l"(b));
}
__device__ __forceinline__ u64 dup2(float a) {
    u64 r; asm("mov.b64 %0, {%1, %1};" : "=l"(r) : "f"(a)); return r;
}
__device__ __forceinline__ void unpack2(u64 v, float &lo, float &hi) {
    asm("mov.b64 {%0, %1}, %2;" : "=f"(lo), "=f"(hi) : "l"(v));
}
__device__ __forceinline__ float tf32r(float a) {
    uint32_t u; asm("cvt.rna.tf32.f32 %0, %1;" : "=r"(u) : "f"(a));
    return __uint_as_float(u);
}
__device__ __forceinline__ void mma_tf32(float* d, const uint32_t* a, uint32_t b0, uint32_t b1) {
    asm volatile(
        "mma.sync.aligned.m16n8k8.row.col.f32.tf32.tf32.f32 "
        "{%0,%1,%2,%3}, {%4,%5,%6,%7}, {%8,%9}, {%0,%1,%2,%3};"
        : "+f"(d[0]), "+f"(d[1]), "+f"(d[2]), "+f"(d[3])
        : "r"(a[0]), "r"(a[1]), "r"(a[2]), "r"(a[3]), "r"(b0), "r"(b1));
}

// ---------------------------------------------------------------- prep
__global__ void prep_kernel(const float* __restrict__ Wc,
                            const long long* __restrict__ lab) {
    int gid = blockIdx.x*256 + threadIdx.x;     // 0..81919
    if (gid < BATCH*OC)      g_pooled_full[gid] = 0.f;
    if (gid < BATCH*TOPK*OC) g_pooled_crop[gid] = 0.f;
    if (gid == 0)            g_njobs = 0;
    if (blockIdx.x < 147) {
        int k = blockIdx.x, c = threadIdx.x;
        g_Wt[k*OC + c] = Wc[c*147 + k];
    }
    // hi/lo tf32 weight fragments: idx = (((ct*19+s)*8+Ml)*32+lane)*4+reg
    if (gid < 2*NFRAG) {
        int reg  = gid & 3;
        int lane = (gid >> 2) & 31;
        int Ml   = (gid >> 7) & 7;
        int ct   = gid / NFRAG;
        int s    = (gid - ct*NFRAG) >> 10;
        int oc = ct*128 + Ml*16 + (lane >> 2) + (reg & 1)*8;
        int k  = s*8 + (lane & 3) + (reg >> 1)*4;
        float wv = (k < 147) ? Wc[oc*147 + k] : 0.f;
        float hi = tf32r(wv);
        g_WfragHi[gid] = hi;
        g_WfragLo[gid] = tf32r(wv - hi);
    }
    if (blockIdx.x == 159) {
        // labels dtype probe: first 1200 int64 words == extent of an int32 buffer
        // of 2400 elems (never OOB). Real int64 labels all lie in [0,91).
        __shared__ int bad;
        if (threadIdx.x == 0) bad = 0;
        __syncthreads();
        for (int i = threadIdx.x; i < 1200; i += 256) {
            long long v = lab[i];
            if (v < 0 || v >= 91) bad = 1;
        }
        __syncthreads();
        if (threadIdx.x == 0) g_lab64 = bad ? 0 : 1;
    }
}

// ---------------------------------------------------------------- top-k: one warp per batch
__global__ void topk_kernel(const float* __restrict__ boxes,
                            const float* __restrict__ scores,
                            const void* __restrict__ labels_raw,
                            float* __restrict__ out) {
    int b = blockIdx.x;
    int t = threadIdx.x;
    int lab64 = g_lab64;
    const int*       l32 = (const int*)labels_raw;
    const long long* l64 = (const long long*)labels_raw;

    float v[10];
    #pragma unroll
    for (int r = 0; r < 10; r++) {
        int i = t + 32*r;
        float s = -INFINITY;
        if (i < NBOX) {
            long long l = lab64 ? l64[b*NBOX + i] : (long long)l32[b*NBOX + i];
            bool veh = (l==2)||(l==3)||(l==4)||(l==6)||(l==8);
            float sc = scores[b*NBOX + i];
            if (veh && sc > 0.8f) s = sc;
        }
        v[r] = s;
    }
    for (int k = 0; k < TOPK; k++) {
        float bv = -INFINITY; int bi = 0x7fffffff;
        #pragma unroll
        for (int r = 0; r < 10; r++) {
            int i = t + 32*r;
            if (v[r] > bv) { bv = v[r]; bi = i; }
        }
        #pragma unroll
        for (int o = 16; o > 0; o >>= 1) {
            float ov = __shfl_down_sync(0xffffffffu, bv, o);
            int   oi = __shfl_down_sync(0xffffffffu, bi, o);
            if (ov > bv || (ov == bv && oi < bi)) { bv = ov; bi = oi; }
        }
        bv = __shfl_sync(0xffffffffu, bv, 0);
        bi = __shfl_sync(0xffffffffu, bi, 0);
        bool valid = (bv != -INFINITY);
        if (valid && (bi & 31) == t) {
            int r = bi >> 5;
            #pragma unroll
            for (int rr = 0; rr < 10; rr++) if (rr == r) v[rr] = -INFINITY;
        }
        if (t == 0) {
            float b0=0.f,b1=0.f,b2=0.f,b3=0.f;
            if (valid) {
                const float* bp = boxes + (b*NBOX + bi)*4;
                b0=bp[0]; b1=bp[1]; b2=bp[2]; b3=bp[3];
            }
            int bk = b*TOPK + k;
            out[OBJ_OFF + bk*4+0] = b0;
            out[OBJ_OFF + bk*4+1] = b1;
            out[OBJ_OFF + bk*4+2] = b2;
            out[OBJ_OFF + bk*4+3] = b3;
            out[VALID_OFF + bk]   = valid ? 1.0f : 0.0f;
            if (valid && b2 > b0 && b3 > b1) {
                int pos = atomicAdd(&g_njobs, 1);
                g_job_box[pos*4+0]=b0; g_job_box[pos*4+1]=b1;
                g_job_box[pos*4+2]=b2; g_job_box[pos*4+3]=b3;
                g_job_b[pos]  = b;
                g_job_bk[pos] = bk;
            }
        }
    }
}

// ---------------------------------------------------------------- RoIAlign (normalized on the fly)
__global__ void sample_kernel(const float* __restrict__ x) {
    int j = blockIdx.x;
    if (j >= g_njobs) return;
    int b = g_job_b[j];
    float bx0 = g_job_box[j*4+0], by0 = g_job_box[j*4+1];
    float bx1 = g_job_box[j*4+2], by1 = g_job_box[j*4+3];
    for (int idx = threadIdx.x; idx < 3*CROPS*CROPS; idx += blockDim.x) {
        int c  = idx >> 12;
        int rem = idx & 4095;
        int yi = rem >> 6, xi = rem & 63;
        float ys = by0 + (yi + 0.5f)*(1.0f/CROPS)*(by1 - by0);
        float xs = bx0 + (xi + 0.5f)*(1.0f/CROPS)*(bx1 - bx0);
        float yf = floorf(ys), xf = floorf(xs);
        float wy = ys - yf,  wx = xs - xf;
        int y0 = min(max((int)yf, 0), HW-1); int y1 = min(y0+1, HW-1);
        int x0 = min(max((int)xf, 0), HW-1); int x1 = min(x0+1, HW-1);
        const float* img = x + ((long)b*3 + c)*HW*HW;
        float m = c_mean[c], is = c_istd[c];
        float Ia = (img[y0*HW + x0]-m)*is, Ib = (img[y0*HW + x1]-m)*is;
        float Ic = (img[y1*HW + x0]-m)*is, Id = (img[y1*HW + x1]-m)*is;
        g_crops[j*(3*CROPS*CROPS) + idx] =
            Ia*(1.f-wy)*(1.f-wx) + Ib*(1.f-wy)*wx + Ic*wy*(1.f-wx) + Id*wy*wx;
    }
}

// ---------------------------------------------------------------- unified conv
// bx < FULL_BLOCKS: tf32 mma fullframe tile (128 oc x 128 px), weights hi+lo split,
// A-fragments double-buffered in registers to hide the L2 latency.
// else: scalar FFMA2 crop tile (exact fp32).
__global__ void __launch_bounds__(256, 2) conv_kernel(const float* __restrict__ x,
                                                      const float* __restrict__ bc) {
    extern __shared__ char smc[];
    int t = threadIdx.x;
    int w = t >> 5, lane = t & 31;
    int bx = blockIdx.x;

    if (bx < FULL_BLOCKS) {
        float* smB = (float*)smc;
        int4*  dec = (int4*)(smc + DEC_OFF);
        int ocg = w & 3, pxg = w >> 2;
        int ct = bx & 1, tile = bx >> 1;
        int oy = tile & 127, b = tile >> 7;
        int c0 = ct*128;

        // decode table: k -> {flat_off, ky, kx, cin}
        if (t < 152) {
            int k = t;
            int cin = k/49; int rr = k - cin*49;
            int ky = rr/7;  int kx = rr - ky*7;
            if (k >= 147) { cin = 0; ky = 0; kx = 0; }
            dec[t] = make_int4(cin*262144 + ky*512 + kx - 1, ky, kx, cin);
        }
        __syncthreads();

        // build fragment-packed im2col (rna-rounded to tf32)
        {
            int k0  = lane & 3;
            int px0 = w*16 + (lane >> 2);
            int iyb = 4*oy - 1;
            int iyb512 = iyb*512;
            const float* xb = x + (long)b*3*262144;
            #pragma unroll 4
            for (int it = 0; it < KSTEPS; it++) {
                float v[4];
                #pragma unroll
                for (int e = 0; e < 4; e++) {
                    int k  = it*8 + k0 + (e & 1)*4;
                    int px = px0 + (e >> 1)*8;
                    float val = 0.f;
                    if (k < 147) {
                        int4 dc = dec[k];
                        int iy = iyb + dc.y;
                        int ix = 4*px - 1 + dc.z;
                        if ((unsigned)iy < 512u && (unsigned)ix < 512u)
                            val = (xb[dc.x + iyb512 + 4*px] - c_mean[dc.w])*c_istd[dc.w];
                    }
                    v[e] = tf32r(val);
                }
                float4* dst = (float4*)smB + (it*8 + w)*32 + lane;
                *dst = make_float4(v[0], v[1], v[2], v[3]);
            }
        }
        __syncthreads();

        float d[2][8][4];
        #pragma unroll
        for (int mt = 0; mt < 2; mt++)
            #pragma unroll
            for (int nt = 0; nt < 8; nt++)
                #pragma unroll
                for (int r = 0; r < 4; r++) d[mt][nt][r] = 0.f;

        const uint4* aH = (const uint4*)g_WfragHi + ((ct*KSTEPS)*8 + ocg*2)*32 + lane;
        const uint4* aL = (const uint4*)g_WfragLo + ((ct*KSTEPS)*8 + ocg*2)*32 + lane;
        const uint4* bf = (const uint4*)smB + (pxg*4)*32 + lane;
        // prologue: load step-0 A fragments
        uint4 nh0 = aH[0], nh1 = aH[32];
        uint4 nl0 = aL[0], nl1 = aL[32];
        #pragma unroll 1
        for (int s = 0; s < KSTEPS; s++) {
            uint4 h0 = nh0, h1 = nh1, l0 = nl0, l1 = nl1;
            // prefetch next step's A fragments (L2 latency hidden under MMAs)
            int sn = (s + 1 < KSTEPS) ? s + 1 : s;
            nh0 = aH[(sn*8)*32];  nh1 = aH[(sn*8 + 1)*32];
            nl0 = aL[(sn*8)*32];  nl1 = aL[(sn*8 + 1)*32];
            uint4 b0 = bf[(s*8)*32];
            uint4 b1 = bf[(s*8 + 1)*32];
            uint4 b2 = bf[(s*8 + 2)*32];
            uint4 b3 = bf[(s*8 + 3)*32];
            const uint32_t* ph0 = (const uint32_t*)&h0;
            const uint32_t* ph1 = (const uint32_t*)&h1;
            const uint32_t* pl0 = (const uint32_t*)&l0;
            const uint32_t* pl1 = (const uint32_t*)&l1;
            mma_tf32(d[0][0], ph0, b0.x, b0.y);  mma_tf32(d[0][0], pl0, b0.x, b0.y);
            mma_tf32(d[0][1], ph0, b0.z, b0.w);  mma_tf32(d[0][1], pl0, b0.z, b0.w);
            mma_tf32(d[0][2], ph0, b1.x, b1.y);  mma_tf32(d[0][2], pl0, b1.x, b1.y);
            mma_tf32(d[0][3], ph0, b1.z, b1.w);  mma_tf32(d[0][3], pl0, b1.z, b1.w);
            mma_tf32(d[0][4], ph0, b2.x, b2.y);  mma_tf32(d[0][4], pl0, b2.x, b2.y);
            mma_tf32(d[0][5], ph0, b2.z, b2.w);  mma_tf32(d[0][5], pl0, b2.z, b2.w);
            mma_tf32(d[0][6], ph0, b3.x, b3.y);  mma_tf32(d[0][6], pl0, b3.x, b3.y);
            mma_tf32(d[0][7], ph0, b3.z, b3.w);  mma_tf32(d[0][7], pl0, b3.z, b3.w);
            mma_tf32(d[1][0], ph1, b0.x, b0.y);  mma_tf32(d[1][0], pl1, b0.x, b0.y);
            mma_tf32(d[1][1], ph1, b0.z, b0.w);  mma_tf32(d[1][1], pl1, b0.z, b0.w);
            mma_tf32(d[1][2], ph1, b1.x, b1.y);  mma_tf32(d[1][2], pl1, b1.x, b1.y);
            mma_tf32(d[1][3], ph1, b1.z, b1.w);  mma_tf32(d[1][3], pl1, b1.z, b1.w);
            mma_tf32(d[1][4], ph1, b2.x, b2.y);  mma_tf32(d[1][4], pl1, b2.x, b2.y);
            mma_tf32(d[1][5], ph1, b2.z, b2.w);  mma_tf32(d[1][5], pl1, b2.z, b2.w);
            mma_tf32(d[1][6], ph1, b3.x, b3.y);  mma_tf32(d[1][6], pl1, b3.x, b3.y);
            mma_tf32(d[1][7], ph1, b3.z, b3.w);  mma_tf32(d[1][7], pl1, b3.z, b3.w);
        }

        // epilogue: bias + relu + pool over px, atomic accumulate
        #pragma unroll
        for (int mt = 0; mt < 2; mt++) {
            int oc_r0 = c0 + ocg*32 + mt*16 + (lane >> 2);
            float bias0 = bc[oc_r0];
            float bias1 = bc[oc_r0 + 8];
            float s0 = 0.f, s1 = 0.f;
            #pragma unroll
            for (int nt = 0; nt < 8; nt++) {
                s0 += fmaxf(d[mt][nt][0] + bias0, 0.f) + fmaxf(d[mt][nt][1] + bias0, 0.f);
                s1 += fmaxf(d[mt][nt][2] + bias1, 0.f) + fmaxf(d[mt][nt][3] + bias1, 0.f);
            }
            s0 += __shfl_xor_sync(0xffffffffu, s0, 1);
            s0 += __shfl_xor_sync(0xffffffffu, s0, 2);
            s1 += __shfl_xor_sync(0xffffffffu, s1, 1);
            s1 += __shfl_xor_sync(0xffffffffu, s1, 2);
            if ((lane & 3) == 0) {
                atomicAdd(&g_pooled_full[b*OC + oc_r0],     s0);
                atomicAdd(&g_pooled_full[b*OC + oc_r0 + 8], s1);
            }
        }
    } else {
        // ------------- crop: half (8 out-rows = 128 px) x 128 channels, exact fp32
        float* sm = (float*)smc;
        int pxg = lane, cg = w;
        int cx2 = bx - FULL_BLOCKS;
        int ct = cx2 & 1; int half = (cx2 >> 1) & 1; int j = cx2 >> 2;
        if (j >= g_njobs) return;
        int c0 = ct*128;
        const float* crop = g_crops + (long)j*(3*CROPS*CROPS);
        int iy0 = half*32 - 1;
        for (int s = t; s < 105*67; s += 256) {
            int row = s / 67; int p = s - row*67;
            int cin = row / 35; int iyl = row - cin*35;
            int cy = iy0 + iyl, cxx = p - 1;
            float v = 0.f;
            if ((unsigned)cy < 64u && (unsigned)cxx < 64u)
                v = crop[(cin*64 + cy)*64 + cxx];
            sm[row*84 + (p&3)*18 + (p>>2)] = v;
        }
        __syncthreads();

        int rowoff[4];
        #pragma unroll
        for (int m = 0; m < 4; m++) {
            int px = pxg + 32*m;
            rowoff[m] = (px >> 4)*4*84 + (px & 15);
        }
        u64 acc[4][8];
        {
            const u64* b2 = (const u64*)(bc + c0 + cg*16);
            #pragma unroll
            for (int i = 0; i < 8; i++) {
                u64 bb = b2[i];
                acc[0][i]=bb; acc[1][i]=bb; acc[2][i]=bb; acc[3][i]=bb;
            }
        }
        const float* wbase = g_Wt + c0 + cg*16;
        for (int cin = 0; cin < 3; cin++) {
            const float* plc = sm + cin*35*84;
            const float* wc  = wbase + cin*49*OC;
            #pragma unroll
            for (int ky = 0; ky < 7; ky++) {
                #pragma unroll
                for (int kx = 0; kx < 7; kx++) {
                    const float* pl = plc + ky*84 + (kx&3)*18 + (kx>>2);
                    float a0 = pl[rowoff[0]], a1 = pl[rowoff[1]];
                    float a2 = pl[rowoff[2]], a3 = pl[rowoff[3]];
                    const ulonglong2* wp = (const ulonglong2*)(wc + (ky*7+kx)*OC);
                    ulonglong2 wA = wp[0], wB = wp[1], wC = wp[2], wD = wp[3];
                    u64 dd;
                    dd = dup2(a0);
                    ffma2(acc[0][0],dd,wA.x); ffma2(acc[0][1],dd,wA.y); ffma2(acc[0][2],dd,wB.x); ffma2(acc[0][3],dd,wB.y);
                    ffma2(acc[0][4],dd,wC.x); ffma2(acc[0][5],dd,wC.y); ffma2(acc[0][6],dd,wD.x); ffma2(acc[0][7],dd,wD.y);
                    dd = dup2(a1);
                    ffma2(acc[1][0],dd,wA.x); ffma2(acc[1][1],dd,wA.y); ffma2(acc[1][2],dd,wB.x); ffma2(acc[1][3],dd,wB.y);
                    ffma2(acc[1][4],dd,wC.x); ffma2(acc[1][5],dd,wC.y); ffma2(acc[1][6],dd,wD.x); ffma2(acc[1][7],dd,wD.y);
                    dd = dup2(a2);
                    ffma2(acc[2][0],dd,wA.x); ffma2(acc[2][1],dd,wA.y); ffma2(acc[2][2],dd,wB.x); ffma2(acc[2][3],dd,wB.y);
                    ffma2(acc[2][4],dd,wC.x); ffma2(acc[2][5],dd,wC.y); ffma2(acc[2][6],dd,wD.x); ffma2(acc[2][7],dd,wD.y);
                    dd = dup2(a3);
                    ffma2(acc[3][0],dd,wA.x); ffma2(acc[3][1],dd,wA.y); ffma2(acc[3][2],dd,wB.x); ffma2(acc[3][3],dd,wB.y);
                    ffma2(acc[3][4],dd,wC.x); ffma2(acc[3][5],dd,wC.y); ffma2(acc[3][6],dd,wD.x); ffma2(acc[3][7],dd,wD.y);
                }
            }
        }
        #pragma unroll
        for (int i = 0; i < 8; i++) {
            float s0 = 0.f, s1 = 0.f;
            #pragma unroll
            for (int m = 0; m < 4; m++) {
                float lo, hi; unpack2(acc[m][i], lo, hi);
                s0 += fmaxf(lo, 0.f); s1 += fmaxf(hi, 0.f);
            }
            #pragma unroll
            for (int o = 16; o > 0; o >>= 1) {
                s0 += __shfl_down_sync(0xffffffffu, s0, o);
                s1 += __shfl_down_sync(0xffffffffu, s1, o);
            }
            if (pxg == 0) {
                atomicAdd(&g_pooled_crop[j*OC + c0 + cg*16 + 2*i],     s0);
                atomicAdd(&g_pooled_crop[j*OC + c0 + cg*16 + 2*i + 1], s1);
            }
        }
    }
}

// ---------------------------------------------------------------- unified FC
__global__ void __launch_bounds__(256) fc_kernel(const float* __restrict__ Wf,
                                                 const float* __restrict__ bf,
                                                 float* __restrict__ out) {
    int y = blockIdx.y, t = threadIdx.x;
    int o = blockIdx.x*256 + t;
    __shared__ float sp[8*OC];
    if (y == 0) {
        for (int s = t; s < BATCH*OC; s += 256)
            sp[s] = g_pooled_full[s] * (1.0f/16384.0f);
        __syncthreads();
        float acc[8] = {0.f,0.f,0.f,0.f,0.f,0.f,0.f,0.f};
        for (int c = 0; c < OC; c++) {
            float w = Wf[(long)c*FCO + o];
            #pragma unroll
            for (int b2 = 0; b2 < 8; b2++) acc[b2] += sp[b2*OC + c] * w;
        }
        float bias = bf[o];
        #pragma unroll
        for (int b2 = 0; b2 < 8; b2++)
            out[FULL_OFF + b2*FCO + o] = acc[b2] + bias;
    } else {
        int nj = g_njobs;
        int j0 = (y - 1)*8;
        if (j0 >= nj) return;
        for (int s = t; s < 8*OC; s += 256) {
            int jj = s >> 8; int c = s & 255;
            int j = j0 + jj;
            sp[s] = (j < nj) ? g_pooled_crop[j*OC + c] * (1.0f/256.0f) : 0.f;
        }
        __syncthreads();
        float acc[8] = {0.f,0.f,0.f,0.f,0.f,0.f,0.f,0.f};
        for (int c = 0; c < OC; c++) {
            float w = Wf[(long)c*FCO + o];
            #pragma unroll
            for (int jj = 0; jj < 8; jj++) acc[jj] += sp[jj*OC + c] * w;
        }
        float bias = bf[o];
        #pragma unroll
        for (int jj = 0; jj < 8; jj++) {
            int j = j0 + jj;
            if (j < nj)
                out[FEAT_OFF + (long)g_job_bk[j]*FCO + o] = acc[jj] + bias;
        }
    }
}

// ---------------------------------------------------------------- launch
extern "C" void kernel_launch(void* const* d_in, const int* in_sizes, int n_in,
                              void* d_out, int out_size) {
    const float* x      = (const float*)d_in[0];
    const float* boxes  = (const float*)d_in[1];
    const float* scores = (const float*)d_in[2];
    const void*  labels = d_in[3];
    const float* Wc     = (const float*)d_in[4];
    const float* bc     = (const float*)d_in[5];
    const float* Wf     = (const float*)d_in[6];
    const float* bf     = (const float*)d_in[7];
    float* out = (float*)d_out;

    cudaFuncSetAttribute(conv_kernel, cudaFuncAttributeMaxDynamicSharedMemorySize, CONV_SMEM);

    prep_kernel<<<320, 256>>>(Wc, (const long long*)labels);
    topk_kernel<<<BATCH, 32>>>(boxes, scores, labels, out);
    cudaMemsetAsync(out + FEAT_OFF, 0, (size_t)BATCH*TOPK*FCO*sizeof(float));
    sample_kernel<<<BATCH*TOPK, 256>>>(x);
    conv_kernel<<<FULL_BLOCKS + CROP_BLOCKS, 256, CONV_SMEM>>>(x, bc);
    fc_kernel<<<dim3(16, 21), 256>>>(Wf, bf, out);
}

// round 10
// speedup vs baseline: 2.5865x; 1.0096x over previous
#include <cuda_runtime.h>
#include <math.h>
#include <stdint.h>

typedef unsigned long long u64;

#define BATCH 8
#define NBOX  300
#define TOPK  20
#define HW    512
#define CROPS 64
#define OC    256
#define FCO   4096

// d_out layout (floats): Objects[8,20,4] | Object_features[8,20,4096] | valid[8,20] | fullframe[8,4096]
#define OBJ_OFF   0
#define FEAT_OFF  640
#define VALID_OFF 656000
#define FULL_OFF  656160

#define KSTEPS 19                      // 147 -> 152 (19 k-steps of 8)
#define NFRAG  (KSTEPS*8*32*4)         // 19456 floats per ct
#define BSMEM_BYTES (KSTEPS*8*32*16)   // 77824 B fragment-packed im2col
#define DEC_OFF  BSMEM_BYTES           // int4[152] decode table
#define CONV_SMEM (BSMEM_BYTES + 152*16)   // 80256 B
#define FULL_BLOCKS 2048
#define CROP_BLOCKS (BATCH*TOPK*4)     // job * 2 halves * 2 ct

__constant__ float c_mean[3] = {0.485f, 0.456f, 0.406f};
__constant__ float c_istd[3] = {1.0f/0.229f, 1.0f/0.224f, 1.0f/0.225f};

__device__ float g_pooled_full[BATCH*OC];
__device__ float g_pooled_crop[BATCH*TOPK*OC];
__device__ float g_crops[BATCH*TOPK*3*CROPS*CROPS];
__device__ __align__(16) float g_Wt[147*OC];         // [k][oc] for scalar crop conv
__device__ __align__(16) float g_WfragHi[2*NFRAG];   // tf32-hi weight fragments
__device__ __align__(16) float g_WfragLo[2*NFRAG];   // tf32-lo weight fragments
__device__ float g_job_box[BATCH*TOPK*4];
__device__ int   g_job_b[BATCH*TOPK];
__device__ int   g_job_bk[BATCH*TOPK];
__device__ int   g_njobs;
__device__ int   g_lab64;

// ---------------------------------------------------------------- helpers
__device__ __forceinline__ void ffma2(u64 &d, u64 a, u64 b) {
    asm("fma.rn.f32x2 %0, %1, %2, %0;" : "+l"(d) : "l"(a), "l"(b));
}
__device__ __forceinline__ u64 dup2(float a) {
    u64 r; asm("mov.b64 %0, {%1, %1};" : "=l"(r) : "f"(a)); return r;
}
__device__ __forceinline__ void unpack2(u64 v, float &lo, float &hi) {
    asm("mov.b64 {%0, %1}, %2;" : "=f"(lo), "=f"(hi) : "l"(v));
}
__device__ __forceinline__ float tf32r(float a) {
    uint32_t u; asm("cvt.rna.tf32.f32 %0, %1;" : "=r"(u) : "f"(a));
    return __uint_as_float(u);
}
__device__ __forceinline__ void mma_tf32(float* d, const uint32_t* a, uint32_t b0, uint32_t b1) {
    asm volatile(
        "mma.sync.aligned.m16n8k8.row.col.f32.tf32.tf32.f32 "
        "{%0,%1,%2,%3}, {%4,%5,%6,%7}, {%8,%9}, {%0,%1,%2,%3};"
        : "+f"(d[0]), "+f"(d[1]), "+f"(d[2]), "+f"(d[3])
        : "r"(a[0]), "r"(a[1]), "r"(a[2]), "r"(a[3]), "r"(b0), "r"(b1));
}

// ---------------------------------------------------------------- prep
__global__ void prep_kernel(const float* __restrict__ Wc,
                            const long long* __restrict__ lab) {
    int gid = blockIdx.x*256 + threadIdx.x;
    if (gid < BATCH*OC)      g_pooled_full[gid] = 0.f;
    if (gid < BATCH*TOPK*OC) g_pooled_crop[gid] = 0.f;
    if (gid == 0)            g_njobs = 0;
    if (blockIdx.x < 147) {
        int k = blockIdx.x, c = threadIdx.x;
        g_Wt[k*OC + c] = Wc[c*147 + k];
    }
    // hi/lo tf32 weight fragments: idx = (((ct*19+s)*8+Ml)*32+lane)*4+reg
    if (gid < 2*NFRAG) {
        int reg  = gid & 3;
        int lane = (gid >> 2) & 31;
        int Ml   = (gid >> 7) & 7;
        int ct   = gid / NFRAG;
        int s    = (gid - ct*NFRAG) >> 10;
        int oc = ct*128 + Ml*16 + (lane >> 2) + (reg & 1)*8;
        int k  = s*8 + (lane & 3) + (reg >> 1)*4;
        float wv = (k < 147) ? Wc[oc*147 + k] : 0.f;
        float hi = tf32r(wv);
        g_WfragHi[gid] = hi;
        g_WfragLo[gid] = tf32r(wv - hi);
    }
    if (blockIdx.x == 159) {
        // labels dtype probe: first 1200 int64 words == extent of an int32 buffer
        // of 2400 elems (never OOB). Real int64 labels all lie in [0,91).
        __shared__ int bad;
        if (threadIdx.x == 0) bad = 0;
        __syncthreads();
        for (int i = threadIdx.x; i < 1200; i += 256) {
            long long v = lab[i];
            if (v < 0 || v >= 91) bad = 1;
        }
        __syncthreads();
        if (threadIdx.x == 0) g_lab64 = bad ? 0 : 1;
    }
}

// ---------------------------------------------------------------- top-k: one warp per batch
__global__ void topk_kernel(const float* __restrict__ boxes,
                            const float* __restrict__ scores,
                            const void* __restrict__ labels_raw,
                            float* __restrict__ out) {
    int b = blockIdx.x;
    int t = threadIdx.x;
    int lab64 = g_lab64;
    const int*       l32 = (const int*)labels_raw;
    const long long* l64 = (const long long*)labels_raw;

    float v[10];
    #pragma unroll
    for (int r = 0; r < 10; r++) {
        int i = t + 32*r;
        float s = -INFINITY;
        if (i < NBOX) {
            long long l = lab64 ? l64[b*NBOX + i] : (long long)l32[b*NBOX + i];
            bool veh = (l==2)||(l==3)||(l==4)||(l==6)||(l==8);
            float sc = scores[b*NBOX + i];
            if (veh && sc > 0.8f) s = sc;
        }
        v[r] = s;
    }
    for (int k = 0; k < TOPK; k++) {
        float bv = -INFINITY; int bi = 0x7fffffff;
        #pragma unroll
        for (int r = 0; r < 10; r++) {
            int i = t + 32*r;
            if (v[r] > bv) { bv = v[r]; bi = i; }
        }
        #pragma unroll
        for (int o = 16; o > 0; o >>= 1) {
            float ov = __shfl_down_sync(0xffffffffu, bv, o);
            int   oi = __shfl_down_sync(0xffffffffu, bi, o);
            if (ov > bv || (ov == bv && oi < bi)) { bv = ov; bi = oi; }
        }
        bv = __shfl_sync(0xffffffffu, bv, 0);
        bi = __shfl_sync(0xffffffffu, bi, 0);
        bool valid = (bv != -INFINITY);
        if (valid && (bi & 31) == t) {
            int r = bi >> 5;
            #pragma unroll
            for (int rr = 0; rr < 10; rr++) if (rr == r) v[rr] = -INFINITY;
        }
        if (t == 0) {
            float b0=0.f,b1=0.f,b2=0.f,b3=0.f;
            if (valid) {
                const float* bp = boxes + (b*NBOX + bi)*4;
                b0=bp[0]; b1=bp[1]; b2=bp[2]; b3=bp[3];
            }
            int bk = b*TOPK + k;
            out[OBJ_OFF + bk*4+0] = b0;
            out[OBJ_OFF + bk*4+1] = b1;
            out[OBJ_OFF + bk*4+2] = b2;
            out[OBJ_OFF + bk*4+3] = b3;
            out[VALID_OFF + bk]   = valid ? 1.0f : 0.0f;
            if (valid && b2 > b0 && b3 > b1) {
                int pos = atomicAdd(&g_njobs, 1);
                g_job_box[pos*4+0]=b0; g_job_box[pos*4+1]=b1;
                g_job_box[pos*4+2]=b2; g_job_box[pos*4+3]=b3;
                g_job_b[pos]  = b;
                g_job_bk[pos] = bk;
            }
        }
    }
}

// ---------------------------------------------------------------- RoIAlign (normalized on the fly)
__global__ void sample_kernel(const float* __restrict__ x) {
    int j = blockIdx.x;
    if (j >= g_njobs) return;
    int b = g_job_b[j];
    float bx0 = g_job_box[j*4+0], by0 = g_job_box[j*4+1];
    float bx1 = g_job_box[j*4+2], by1 = g_job_box[j*4+3];
    for (int idx = threadIdx.x; idx < 3*CROPS*CROPS; idx += blockDim.x) {
        int c  = idx >> 12;
        int rem = idx & 4095;
        int yi = rem >> 6, xi = rem & 63;
        float ys = by0 + (yi + 0.5f)*(1.0f/CROPS)*(by1 - by0);
        float xs = bx0 + (xi + 0.5f)*(1.0f/CROPS)*(bx1 - bx0);
        float yf = floorf(ys), xf = floorf(xs);
        float wy = ys - yf,  wx = xs - xf;
        int y0 = min(max((int)yf, 0), HW-1); int y1 = min(y0+1, HW-1);
        int x0 = min(max((int)xf, 0), HW-1); int x1 = min(x0+1, HW-1);
        const float* img = x + ((long)b*3 + c)*HW*HW;
        float m = c_mean[c], is = c_istd[c];
        float Ia = (img[y0*HW + x0]-m)*is, Ib = (img[y0*HW + x1]-m)*is;
        float Ic = (img[y1*HW + x0]-m)*is, Id = (img[y1*HW + x1]-m)*is;
        g_crops[j*(3*CROPS*CROPS) + idx] =
            Ia*(1.f-wy)*(1.f-wx) + Ib*(1.f-wy)*wx + Ic*wy*(1.f-wx) + Id*wy*wx;
    }
}

// ---------------------------------------------------------------- unified conv
// bx < FULL_BLOCKS: tf32 mma fullframe tile (128 oc x 128 px), weights hi+lo split.
// MMA schedule: all 16 independent hi-MMAs, then all 16 lo-MMAs (no RAW stalls).
// else: scalar FFMA2 crop tile (exact fp32).
__global__ void __launch_bounds__(256, 2) conv_kernel(const float* __restrict__ x,
                                                      const float* __restrict__ bc) {
    extern __shared__ char smc[];
    int t = threadIdx.x;
    int w = t >> 5, lane = t & 31;
    int bx = blockIdx.x;

    if (bx < FULL_BLOCKS) {
        float* smB = (float*)smc;
        int4*  dec = (int4*)(smc + DEC_OFF);
        int ocg = w & 3, pxg = w >> 2;
        int ct = bx & 1, tile = bx >> 1;
        int oy = tile & 127, b = tile >> 7;
        int c0 = ct*128;

        // decode table: k -> {flat_off, ky, kx, cin}
        if (t < 152) {
            int k = t;
            int cin = k/49; int rr = k - cin*49;
            int ky = rr/7;  int kx = rr - ky*7;
            if (k >= 147) { cin = 0; ky = 0; kx = 0; }
            dec[t] = make_int4(cin*262144 + ky*512 + kx - 1, ky, kx, cin);
        }
        __syncthreads();

        // build fragment-packed im2col (rna-rounded to tf32)
        {
            int k0  = lane & 3;
            int px0 = w*16 + (lane >> 2);
            int iyb = 4*oy - 1;
            int iyb512 = iyb*512;
            const float* xb = x + (long)b*3*262144;
            #pragma unroll 4
            for (int it = 0; it < KSTEPS; it++) {
                float v[4];
                #pragma unroll
                for (int e = 0; e < 4; e++) {
                    int k  = it*8 + k0 + (e & 1)*4;
                    int px = px0 + (e >> 1)*8;
                    float val = 0.f;
                    if (k < 147) {
                        int4 dc = dec[k];
                        int iy = iyb + dc.y;
                        int ix = 4*px - 1 + dc.z;
                        if ((unsigned)iy < 512u && (unsigned)ix < 512u)
                            val = (xb[dc.x + iyb512 + 4*px] - c_mean[dc.w])*c_istd[dc.w];
                    }
                    v[e] = tf32r(val);
                }
                float4* dst = (float4*)smB + (it*8 + w)*32 + lane;
                *dst = make_float4(v[0], v[1], v[2], v[3]);
            }
        }
        __syncthreads();

        float d[2][8][4];
        #pragma unroll
        for (int mt = 0; mt < 2; mt++)
            #pragma unroll
            for (int nt = 0; nt < 8; nt++)
                #pragma unroll
                for (int r = 0; r < 4; r++) d[mt][nt][r] = 0.f;

        const uint4* aH = (const uint4*)g_WfragHi + ((ct*KSTEPS)*8 + ocg*2)*32 + lane;
        const uint4* aL = (const uint4*)g_WfragLo + ((ct*KSTEPS)*8 + ocg*2)*32 + lane;
        const uint4* bf = (const uint4*)smB + (pxg*4)*32 + lane;
        uint4 nh0 = aH[0], nh1 = aH[32];
        uint4 nl0 = aL[0], nl1 = aL[32];
        #pragma unroll 1
        for (int s = 0; s < KSTEPS; s++) {
            uint4 h0 = nh0, h1 = nh1, l0 = nl0, l1 = nl1;
            int sn = (s + 1 < KSTEPS) ? s + 1 : s;
            nh0 = aH[(sn*8)*32];  nh1 = aH[(sn*8 + 1)*32];
            nl0 = aL[(sn*8)*32];  nl1 = aL[(sn*8 + 1)*32];
            uint4 b0 = bf[(s*8)*32];
            uint4 b1 = bf[(s*8 + 1)*32];
            uint4 b2 = bf[(s*8 + 2)*32];
            uint4 b3 = bf[(s*8 + 3)*32];
            const uint32_t* ph0 = (const uint32_t*)&h0;
            const uint32_t* ph1 = (const uint32_t*)&h1;
            const uint32_t* pl0 = (const uint32_t*)&l0;
            const uint32_t* pl1 = (const uint32_t*)&l1;
            // 16 independent hi-MMAs (distinct accumulators) ...
            mma_tf32(d[0][0], ph0, b0.x, b0.y);
            mma_tf32(d[0][1], ph0, b0.z, b0.w);
            mma_tf32(d[0][2], ph0, b1.x, b1.y);
            mma_tf32(d[0][3], ph0, b1.z, b1.w);
            mma_tf32(d[0][4], ph0, b2.x, b2.y);
            mma_tf32(d[0][5], ph0, b2.z, b2.w);
            mma_tf32(d[0][6], ph0, b3.x, b3.y);
            mma_tf32(d[0][7], ph0, b3.z, b3.w);
            mma_tf32(d[1][0], ph1, b0.x, b0.y);
            mma_tf32(d[1][1], ph1, b0.z, b0.w);
            mma_tf32(d[1][2], ph1, b1.x, b1.y);
            mma_tf32(d[1][3], ph1, b1.z, b1.w);
            mma_tf32(d[1][4], ph1, b2.x, b2.y);
            mma_tf32(d[1][5], ph1, b2.z, b2.w);
            mma_tf32(d[1][6], ph1, b3.x, b3.y);
            mma_tf32(d[1][7], ph1, b3.z, b3.w);
            // ... then 16 lo-MMAs; each is 16 issues after its hi partner
            mma_tf32(d[0][0], pl0, b0.x, b0.y);
            mma_tf32(d[0][1], pl0, b0.z, b0.w);
            mma_tf32(d[0][2], pl0, b1.x, b1.y);
            mma_tf32(d[0][3], pl0, b1.z, b1.w);
            mma_tf32(d[0][4], pl0, b2.x, b2.y);
            mma_tf32(d[0][5], pl0, b2.z, b2.w);
            mma_tf32(d[0][6], pl0, b3.x, b3.y);
            mma_tf32(d[0][7], pl0, b3.z, b3.w);
            mma_tf32(d[1][0], pl1, b0.x, b0.y);
            mma_tf32(d[1][1], pl1, b0.z, b0.w);
            mma_tf32(d[1][2], pl1, b1.x, b1.y);
            mma_tf32(d[1][3], pl1, b1.z, b1.w);
            mma_tf32(d[1][4], pl1, b2.x, b2.y);
            mma_tf32(d[1][5], pl1, b2.z, b2.w);
            mma_tf32(d[1][6], pl1, b3.x, b3.y);
            mma_tf32(d[1][7], pl1, b3.z, b3.w);
        }

        // epilogue: bias + relu + pool over px, atomic accumulate
        #pragma unroll
        for (int mt = 0; mt < 2; mt++) {
            int oc_r0 = c0 + ocg*32 + mt*16 + (lane >> 2);
            float bias0 = bc[oc_r0];
            float bias1 = bc[oc_r0 + 8];
            float s0 = 0.f, s1 = 0.f;
            #pragma unroll
            for (int nt = 0; nt < 8; nt++) {
                s0 += fmaxf(d[mt][nt][0] + bias0, 0.f) + fmaxf(d[mt][nt][1] + bias0, 0.f);
                s1 += fmaxf(d[mt][nt][2] + bias1, 0.f) + fmaxf(d[mt][nt][3] + bias1, 0.f);
            }
            s0 += __shfl_xor_sync(0xffffffffu, s0, 1);
            s0 += __shfl_xor_sync(0xffffffffu, s0, 2);
            s1 += __shfl_xor_sync(0xffffffffu, s1, 1);
            s1 += __shfl_xor_sync(0xffffffffu, s1, 2);
            if ((lane & 3) == 0) {
                atomicAdd(&g_pooled_full[b*OC + oc_r0],     s0);
                atomicAdd(&g_pooled_full[b*OC + oc_r0 + 8], s1);
            }
        }
    } else {
        // ------------- crop: half (8 out-rows = 128 px) x 128 channels, exact fp32
        float* sm = (float*)smc;
        int pxg = lane, cg = w;
        int cx2 = bx - FULL_BLOCKS;
        int ct = cx2 & 1; int half = (cx2 >> 1) & 1; int j = cx2 >> 2;
        if (j >= g_njobs) return;
        int c0 = ct*128;
        const float* crop = g_crops + (long)j*(3*CROPS*CROPS);
        int iy0 = half*32 - 1;
        for (int s = t; s < 105*67; s += 256) {
            int row = s / 67; int p = s - row*67;
            int cin = row / 35; int iyl = row - cin*35;
            int cy = iy0 + iyl, cxx = p - 1;
            float v = 0.f;
            if ((unsigned)cy < 64u && (unsigned)cxx < 64u)
                v = crop[(cin*64 + cy)*64 + cxx];
            sm[row*84 + (p&3)*18 + (p>>2)] = v;
        }
        __syncthreads();

        int rowoff[4];
        #pragma unroll
        for (int m = 0; m < 4; m++) {
            int px = pxg + 32*m;
            rowoff[m] = (px >> 4)*4*84 + (px & 15);
        }
        u64 acc[4][8];
        {
            const u64* b2 = (const u64*)(bc + c0 + cg*16);
            #pragma unroll
            for (int i = 0; i < 8; i++) {
                u64 bb = b2[i];
                acc[0][i]=bb; acc[1][i]=bb; acc[2][i]=bb; acc[3][i]=bb;
            }
        }
        const float* wbase = g_Wt + c0 + cg*16;
        for (int cin = 0; cin < 3; cin++) {
            const float* plc = sm + cin*35*84;
            const float* wc  = wbase + cin*49*OC;
            #pragma unroll
            for (int ky = 0; ky < 7; ky++) {
                #pragma unroll
                for (int kx = 0; kx < 7; kx++) {
                    const float* pl = plc + ky*84 + (kx&3)*18 + (kx>>2);
                    float a0 = pl[rowoff[0]], a1 = pl[rowoff[1]];
                    float a2 = pl[rowoff[2]], a3 = pl[rowoff[3]];
                    const ulonglong2* wp = (const ulonglong2*)(wc + (ky*7+kx)*OC);
                    ulonglong2 wA = wp[0], wB = wp[1], wC = wp[2], wD = wp[3];
                    u64 dd;
                    dd = dup2(a0);
                    ffma2(acc[0][0],dd,wA.x); ffma2(acc[0][1],dd,wA.y); ffma2(acc[0][2],dd,wB.x); ffma2(acc[0][3],dd,wB.y);
                    ffma2(acc[0][4],dd,wC.x); ffma2(acc[0][5],dd,wC.y); ffma2(acc[0][6],dd,wD.x); ffma2(acc[0][7],dd,wD.y);
                    dd = dup2(a1);
                    ffma2(acc[1][0],dd,wA.x); ffma2(acc[1][1],dd,wA.y); ffma2(acc[1][2],dd,wB.x); ffma2(acc[1][3],dd,wB.y);
                    ffma2(acc[1][4],dd,wC.x); ffma2(acc[1][5],dd,wC.y); ffma2(acc[1][6],dd,wD.x); ffma2(acc[1][7],dd,wD.y);
                    dd = dup2(a2);
                    ffma2(acc[2][0],dd,wA.x); ffma2(acc[2][1],dd,wA.y); ffma2(acc[2][2],dd,wB.x); ffma2(acc[2][3],dd,wB.y);
                    ffma2(acc[2][4],dd,wC.x); ffma2(acc[2][5],dd,wC.y); ffma2(acc[2][6],dd,wD.x); ffma2(acc[2][7],dd,wD.y);
                    dd = dup2(a3);
                    ffma2(acc[3][0],dd,wA.x); ffma2(acc[3][1],dd,wA.y); ffma2(acc[3][2],dd,wB.x); ffma2(acc[3][3],dd,wB.y);
                    ffma2(acc[3][4],dd,wC.x); ffma2(acc[3][5],dd,wC.y); ffma2(acc[3][6],dd,wD.x); ffma2(acc[3][7],dd,wD.y);
                }
            }
        }
        #pragma unroll
        for (int i = 0; i < 8; i++) {
            float s0 = 0.f, s1 = 0.f;
            #pragma unroll
            for (int m = 0; m < 4; m++) {
                float lo, hi; unpack2(acc[m][i], lo, hi);
                s0 += fmaxf(lo, 0.f); s1 += fmaxf(hi, 0.f);
            }
            #pragma unroll
            for (int o = 16; o > 0; o >>= 1) {
                s0 += __shfl_down_sync(0xffffffffu, s0, o);
                s1 += __shfl_down_sync(0xffffffffu, s1, o);
            }
            if (pxg == 0) {
                atomicAdd(&g_pooled_crop[j*OC + c0 + cg*16 + 2*i],     s0);
                atomicAdd(&g_pooled_crop[j*OC + c0 + cg*16 + 2*i + 1], s1);
            }
        }
    }
}

// ---------------------------------------------------------------- unified FC
__global__ void __launch_bounds__(256) fc_kernel(const float* __restrict__ Wf,
                                                 const float* __restrict__ bf,
                                                 float* __restrict__ out) {
    int y = blockIdx.y, t = threadIdx.x;
    int o = blockIdx.x*256 + t;
    __shared__ float sp[8*OC];
    if (y == 0) {
        for (int s = t; s < BATCH*OC; s += 256)
            sp[s] = g_pooled_full[s] * (1.0f/16384.0f);
        __syncthreads();
        float acc[8] = {0.f,0.f,0.f,0.f,0.f,0.f,0.f,0.f};
        for (int c = 0; c < OC; c++) {
            float w = Wf[(long)c*FCO + o];
            #pragma unroll
            for (int b2 = 0; b2 < 8; b2++) acc[b2] += sp[b2*OC + c] * w;
        }
        float bias = bf[o];
        #pragma unroll
        for (int b2 = 0; b2 < 8; b2++)
            out[FULL_OFF + b2*FCO + o] = acc[b2] + bias;
    } else {
        int nj = g_njobs;
        int j0 = (y - 1)*8;
        if (j0 >= nj) return;
        for (int s = t; s < 8*OC; s += 256) {
            int jj = s >> 8; int c = s & 255;
            int j = j0 + jj;
            sp[s] = (j < nj) ? g_pooled_crop[j*OC + c] * (1.0f/256.0f) : 0.f;
        }
        __syncthreads();
        float acc[8] = {0.f,0.f,0.f,0.f,0.f,0.f,0.f,0.f};
        for (int c = 0; c < OC; c++) {
            float w = Wf[(long)c*FCO + o];
            #pragma unroll
            for (int jj = 0; jj < 8; jj++) acc[jj] += sp[jj*OC + c] * w;
        }
        float bias = bf[o];
        #pragma unroll
        for (int jj = 0; jj < 8; jj++) {
            int j = j0 + jj;
            if (j < nj)
                out[FEAT_OFF + (long)g_job_bk[j]*FCO + o] = acc[jj] + bias;
        }
    }
}

// ---------------------------------------------------------------- launch
extern "C" void kernel_launch(void* const* d_in, const int* in_sizes, int n_in,
                              void* d_out, int out_size) {
    const float* x      = (const float*)d_in[0];
    const float* boxes  = (const float*)d_in[1];
    const float* scores = (const float*)d_in[2];
    const void*  labels = d_in[3];
    const float* Wc     = (const float*)d_in[4];
    const float* bc     = (const float*)d_in[5];
    const float* Wf     = (const float*)d_in[6];
    const float* bf     = (const float*)d_in[7];
    float* out = (float*)d_out;

    cudaFuncSetAttribute(conv_kernel, cudaFuncAttributeMaxDynamicSharedMemorySize, CONV_SMEM);

    prep_kernel<<<320, 256>>>(Wc, (const long long*)labels);
    topk_kernel<<<BATCH, 32>>>(boxes, scores, labels, out);
    cudaMemsetAsync(out + FEAT_OFF, 0, (size_t)BATCH*TOPK*FCO*sizeof(float));
    sample_kernel<<<BATCH*TOPK, 256>>>(x);
    conv_kernel<<<FULL_BLOCKS + CROP_BLOCKS, 256, CONV_SMEM>>>(x, bc);
    fc_kernel<<<dim3(16, 21), 256>>>(Wf, bf, out);
}